// round 6
// baseline (speedup 1.0000x reference)
#include <cuda_runtime.h>
#include <math.h>
#include <stdint.h>

// ---------------- problem constants ----------------
constexpr int BB = 32, TT = 256, VV = 30522, CC = 768, HH = 8, LL = 10;
constexpr int HS = CC / HH;     // 96
constexpr int FFD = 4 * CC;     // 3072
constexpr int BT = BB * TT;     // 8192
constexpr float LN_EPS = 1e-5f;

// ---------------- scratch ----------------
__device__ float g_x[BT * CC];
__device__ float g_h[BT * CC];
__device__ float g_q[BT * CC];          // [B,H,T,HS]
__device__ float g_k[BT * CC];          // [B,H,T,HS]
__device__ float g_v[BT * CC];          // [B,H,T,HS]
__device__ float g_att[(size_t)BB * HH * TT * TT];
__device__ float g_a[BT * CC];          // [B,H,T,HS]
__device__ float g_ff[(size_t)BT * FFD];
__device__ float g_rowloss[BT];

__device__ __forceinline__ float to_tf32(float x) {
    uint32_t u;
    asm("cvt.rna.tf32.f32 %0, %1;" : "=r"(u) : "f"(x));
    return __uint_as_float(u);
}

__device__ __forceinline__ void mma_tf32(float d[4], const uint32_t a[4], const uint32_t b[2]) {
    asm volatile(
        "mma.sync.aligned.m16n8k8.row.col.f32.tf32.tf32.f32 "
        "{%0,%1,%2,%3}, {%4,%5,%6,%7}, {%8,%9}, {%0,%1,%2,%3};\n"
        : "+f"(d[0]), "+f"(d[1]), "+f"(d[2]), "+f"(d[3])
        : "r"(a[0]), "r"(a[1]), "r"(a[2]), "r"(a[3]), "r"(b[0]), "r"(b[1]));
}

// ---------------- embedding ----------------
__global__ void embed_kernel(const int* __restrict__ idx,
                             const float* __restrict__ tok,
                             const float* __restrict__ pos,
                             float* __restrict__ x) {
    int i = blockIdx.x * blockDim.x + threadIdx.x;
    if (i >= BT * CC) return;
    int bt = i / CC, c = i % CC;
    int t = bt % TT;
    x[i] = tok[(size_t)idx[bt] * CC + c] + pos[(size_t)t * CC + c];
}

// ---------------- layernorm ----------------
__global__ void ln_kernel(const float* __restrict__ x,
                          const float* __restrict__ g,
                          const float* __restrict__ b,
                          float* __restrict__ out) {
    int row = blockIdx.x;
    const float* xr = x + (size_t)row * CC;
    float* orow = out + (size_t)row * CC;
    __shared__ float red[256];
    __shared__ float s_mu, s_inv;
    int tid = threadIdx.x;

    float s = 0.f;
    for (int c = tid; c < CC; c += 256) s += xr[c];
    red[tid] = s; __syncthreads();
    for (int st = 128; st > 0; st >>= 1) { if (tid < st) red[tid] += red[tid + st]; __syncthreads(); }
    if (tid == 0) s_mu = red[0] / CC;
    __syncthreads();
    float mu = s_mu;

    float v = 0.f;
    for (int c = tid; c < CC; c += 256) { float d = xr[c] - mu; v += d * d; }
    red[tid] = v; __syncthreads();
    for (int st = 128; st > 0; st >>= 1) { if (tid < st) red[tid] += red[tid + st]; __syncthreads(); }
    if (tid == 0) s_inv = rsqrtf(red[0] / CC + LN_EPS);
    __syncthreads();
    float inv = s_inv;

    for (int c = tid; c < CC; c += 256)
        orow[c] = (xr[c] - mu) * inv * g[c] + b[c];
}

// ---------------- tensor-core GEMM: BM=64 BN=256, warp tile 64x64 ----------------
// C[M,N] = alpha * A @ B (+bias)(+relu)(+=C)
// TB:   B gmem [N,K] (A @ B^T)
// QKV:  scatter C into [B,H,T,HS];  AQKV: gather A from [B,H,T,HS]
// grid: x = N-tiles (BN=256), y = M-tiles (BM=64), z = batch
// All call sites: M % 64 == 0, K % 16 == 0.
template<bool TB, bool BIAS, bool RELU, bool ACC, bool QKV, bool AQKV>
__global__ __launch_bounds__(128, 2)
void gemm_tc(const float* __restrict__ A, const float* __restrict__ Bm,
             const float* __restrict__ bias, float* __restrict__ Cm,
             int M, int N, int K, float alpha,
             size_t sA, size_t sB, size_t sC) {
    constexpr int BM = 64, BN = 256, BK = 16;
    __shared__ float As[BM][BK + 4];     // stride 20 (frag loads conflict-free)
    __shared__ float Bs[BK][BN + 8];     // stride 264 (frag loads conflict-free)

    const float* Ab = A + (size_t)blockIdx.z * sA;
    const float* Bb = Bm + (size_t)blockIdx.z * sB;
    float* Cb = Cm + (size_t)blockIdx.z * sC;

    int bm = blockIdx.y * BM;
    int bn = blockIdx.x * BN;
    int tid = threadIdx.x;
    int wid = tid >> 5, lane = tid & 31;
    int wn = wid * 64;               // 4 warps along N
    int gq = lane >> 2;              // 0..7
    int cq = lane & 3;               // 0..3

    const bool bvec = (!TB) && (bn + BN <= N) && ((N & 3) == 0);

    float acc[4][8][4];
    #pragma unroll
    for (int i = 0; i < 4; i++)
        #pragma unroll
        for (int j = 0; j < 8; j++)
            #pragma unroll
            for (int t = 0; t < 4; t++) acc[i][j][t] = 0.f;

    float4 rA[2], rB[8];

    auto loadA = [&](int k0) {
        #pragma unroll
        for (int r = 0; r < 2; r++) {
            int id = tid + r * 128;            // 0..255 float4 slots
            int m = id >> 2, kk = (id & 3) * 4;
            int row = bm + m, gk = k0 + kk;
            const float* src;
            if (AQKV) {
                int b = row / TT, t = row % TT, h = gk / HS, d = gk % HS;
                src = &Ab[(((size_t)b * HH + h) * TT + t) * HS + d];
            } else {
                src = &Ab[(size_t)row * K + gk];
            }
            rA[r] = *reinterpret_cast<const float4*>(src);
        }
    };
    auto storeA = [&]() {
        #pragma unroll
        for (int r = 0; r < 2; r++) {
            int id = tid + r * 128;
            int m = id >> 2, kk = (id & 3) * 4;
            As[m][kk + 0] = to_tf32(rA[r].x);
            As[m][kk + 1] = to_tf32(rA[r].y);
            As[m][kk + 2] = to_tf32(rA[r].z);
            As[m][kk + 3] = to_tf32(rA[r].w);
        }
    };
    auto loadB = [&](int k0) {
        if (!TB) {
            #pragma unroll
            for (int r = 0; r < 8; r++) {
                int id = tid + r * 128;        // 0..1023
                int kk = id >> 6;              // 0..15
                int n4 = (id & 63) * 4;        // 0..252
                if (bvec) {
                    rB[r] = *reinterpret_cast<const float4*>(&Bb[(size_t)(k0 + kk) * N + bn + n4]);
                } else {
                    float tmp[4];
                    #pragma unroll
                    for (int j = 0; j < 4; j++) {
                        int gn = bn + n4 + j;
                        tmp[j] = (gn < N) ? Bb[(size_t)(k0 + kk) * N + gn] : 0.f;
                    }
                    rB[r] = make_float4(tmp[0], tmp[1], tmp[2], tmp[3]);
                }
            }
        } else {
            #pragma unroll
            for (int r = 0; r < 8; r++) {
                int id = tid + r * 128;
                int n = id >> 2;               // 0..255
                int kk = (id & 3) * 4;
                if (bn + n < N) {
                    rB[r] = *reinterpret_cast<const float4*>(&Bb[(size_t)(bn + n) * K + k0 + kk]);
                } else {
                    rB[r] = make_float4(0.f, 0.f, 0.f, 0.f);
                }
            }
        }
    };
    auto storeB = [&]() {
        if (!TB) {
            #pragma unroll
            for (int r = 0; r < 8; r++) {
                int id = tid + r * 128;
                int kk = id >> 6;
                int n4 = (id & 63) * 4;
                float4 v;
                v.x = to_tf32(rB[r].x); v.y = to_tf32(rB[r].y);
                v.z = to_tf32(rB[r].z); v.w = to_tf32(rB[r].w);
                *reinterpret_cast<float4*>(&Bs[kk][n4]) = v;
            }
        } else {
            #pragma unroll
            for (int r = 0; r < 8; r++) {
                int id = tid + r * 128;
                int n = id >> 2;
                int kk = (id & 3) * 4;
                Bs[kk + 0][n] = to_tf32(rB[r].x);
                Bs[kk + 1][n] = to_tf32(rB[r].y);
                Bs[kk + 2][n] = to_tf32(rB[r].z);
                Bs[kk + 3][n] = to_tf32(rB[r].w);
            }
        }
    };

    // prologue
    loadA(0); loadB(0);
    storeA(); storeB();
    __syncthreads();

    for (int k0 = 0; k0 < K; k0 += BK) {
        bool has_next = (k0 + BK) < K;
        if (has_next) { loadA(k0 + BK); loadB(k0 + BK); }   // LDGs fly over MMAs

        #pragma unroll
        for (int kk = 0; kk < BK; kk += 8) {
            uint32_t af[4][4];
            uint32_t bf[8][2];
            #pragma unroll
            for (int i = 0; i < 4; i++) {
                int mr = i * 16;
                af[i][0] = __float_as_uint(As[mr + gq][kk + cq]);
                af[i][1] = __float_as_uint(As[mr + gq + 8][kk + cq]);
                af[i][2] = __float_as_uint(As[mr + gq][kk + cq + 4]);
                af[i][3] = __float_as_uint(As[mr + gq + 8][kk + cq + 4]);
            }
            #pragma unroll
            for (int j = 0; j < 8; j++) {
                int nc = wn + j * 8 + gq;
                bf[j][0] = __float_as_uint(Bs[kk + cq][nc]);
                bf[j][1] = __float_as_uint(Bs[kk + cq + 4][nc]);
            }
            #pragma unroll
            for (int i = 0; i < 4; i++)
                #pragma unroll
                for (int j = 0; j < 8; j++)
                    mma_tf32(acc[i][j], af[i], bf[j]);
        }

        __syncthreads();
        if (has_next) {
            storeA(); storeB();
            __syncthreads();
        }
    }

    // epilogue
    #pragma unroll
    for (int i = 0; i < 4; i++) {
        int r0 = bm + i * 16 + gq;
        #pragma unroll
        for (int j = 0; j < 8; j++) {
            int c0 = bn + wn + j * 8 + cq * 2;
            if (c0 >= N) continue;
            #pragma unroll
            for (int half = 0; half < 2; half++) {
                int row = r0 + half * 8;
                float v0 = acc[i][j][half * 2 + 0] * alpha;
                float v1 = acc[i][j][half * 2 + 1] * alpha;
                if (BIAS) { v0 += bias[c0]; v1 += bias[c0 + 1]; }
                if (RELU) { v0 = fmaxf(v0, 0.f); v1 = fmaxf(v1, 0.f); }
                size_t oidx;
                if (QKV) {
                    int b = row / TT, t = row % TT, h = c0 / HS, d = c0 % HS;
                    oidx = (((size_t)b * HH + h) * TT + t) * HS + d;
                } else {
                    oidx = (size_t)row * N + c0;
                }
                if (ACC) {
                    float2 old = *reinterpret_cast<float2*>(&Cb[oidx]);
                    v0 += old.x; v1 += old.y;
                }
                *reinterpret_cast<float2*>(&Cb[oidx]) = make_float2(v0, v1);
            }
        }
    }
}

// ---------------- causal softmax: one warp per row ----------------
__global__ void softmax_kernel(float* __restrict__ att) {
    int warp = threadIdx.x >> 5, lane = threadIdx.x & 31;
    size_t row = (size_t)blockIdx.x * 8 + warp;
    int qi = (int)(row % TT);
    float* w = att + row * (size_t)TT;

    int i0 = lane * 4, i1 = 128 + lane * 4;
    float4 a0 = *reinterpret_cast<float4*>(&w[i0]);
    float4 a1 = *reinterpret_cast<float4*>(&w[i1]);
    float v[8] = {a0.x, a0.y, a0.z, a0.w, a1.x, a1.y, a1.z, a1.w};
    int base[2] = {i0, i1};

    float mx = -1e30f;
    #pragma unroll
    for (int h = 0; h < 2; h++)
        #pragma unroll
        for (int j = 0; j < 4; j++)
            if (base[h] + j <= qi) mx = fmaxf(mx, v[h * 4 + j]);
    #pragma unroll
    for (int s = 16; s > 0; s >>= 1) mx = fmaxf(mx, __shfl_xor_sync(0xffffffffu, mx, s));

    float e[8];
    float sum = 0.f;
    #pragma unroll
    for (int h = 0; h < 2; h++)
        #pragma unroll
        for (int j = 0; j < 4; j++) {
            int idx = h * 4 + j;
            e[idx] = (base[h] + j <= qi) ? expf(v[idx] - mx) : 0.f;
            sum += e[idx];
        }
    #pragma unroll
    for (int s = 16; s > 0; s >>= 1) sum += __shfl_xor_sync(0xffffffffu, sum, s);
    float inv = 1.f / sum;

    *reinterpret_cast<float4*>(&w[i0]) = make_float4(e[0] * inv, e[1] * inv, e[2] * inv, e[3] * inv);
    *reinterpret_cast<float4*>(&w[i1]) = make_float4(e[4] * inv, e[5] * inv, e[6] * inv, e[7] * inv);
}

// ---------------- loss ----------------
__global__ void rowloss_kernel(const float* __restrict__ logits,
                               const int* __restrict__ targets,
                               float* __restrict__ rowloss) {
    int r = blockIdx.x;
    const float* lr = logits + (size_t)r * VV;
    int tid = threadIdx.x;
    __shared__ float red[256];
    __shared__ float s_mx;

    float mx = -1e30f;
    for (int c = tid; c < VV; c += 256) mx = fmaxf(mx, lr[c]);
    red[tid] = mx; __syncthreads();
    for (int st = 128; st > 0; st >>= 1) { if (tid < st) red[tid] = fmaxf(red[tid], red[tid + st]); __syncthreads(); }
    if (tid == 0) s_mx = red[0];
    __syncthreads();
    mx = s_mx;

    float s = 0.f;
    for (int c = tid; c < VV; c += 256) s += expf(lr[c] - mx);
    red[tid] = s; __syncthreads();
    for (int st = 128; st > 0; st >>= 1) { if (tid < st) red[tid] += red[tid + st]; __syncthreads(); }
    if (tid == 0) {
        int t = targets[r];
        rowloss[r] = -(lr[t] - mx - logf(red[0]));
    }
}

__global__ void lossreduce_kernel(const float* __restrict__ rowloss, float* __restrict__ out) {
    __shared__ float red[256];
    int tid = threadIdx.x;
    float s = 0.f;
    for (int r = tid; r < BT; r += 256) s += rowloss[r];
    red[tid] = s; __syncthreads();
    for (int st = 128; st > 0; st >>= 1) { if (tid < st) red[tid] += red[tid + st]; __syncthreads(); }
    if (tid == 0) out[0] = red[0] / BT;
}

// ---------------- host ----------------
static inline dim3 ggrid(int M, int N, int batch) {
    return dim3((N + 255) / 256, M / 64, batch);
}

extern "C" void kernel_launch(void* const* d_in, const int* in_sizes, int n_in,
                              void* d_out, int out_size) {
    const int*   idx     = (const int*)  d_in[0];
    const int*   targets = (const int*)  d_in[1];
    const float* tok_emb = (const float*)d_in[2];
    const float* pos_emb = (const float*)d_in[3];
    const float* Wq      = (const float*)d_in[4];
    const float* Wk      = (const float*)d_in[5];
    const float* Wv      = (const float*)d_in[6];
    const float* Wproj   = (const float*)d_in[7];
    const float* bproj   = (const float*)d_in[8];
    const float* W1      = (const float*)d_in[9];
    const float* b1      = (const float*)d_in[10];
    const float* W2      = (const float*)d_in[11];
    const float* b2      = (const float*)d_in[12];
    const float* ln1_g   = (const float*)d_in[13];
    const float* ln1_b   = (const float*)d_in[14];
    const float* ln2_g   = (const float*)d_in[15];
    const float* ln2_b   = (const float*)d_in[16];
    const float* lnf_g   = (const float*)d_in[17];
    const float* lnf_b   = (const float*)d_in[18];
    const float* Wlm     = (const float*)d_in[19];
    const float* blm     = (const float*)d_in[20];
    float* out = (float*)d_out;

    float* x  = nullptr; cudaGetSymbolAddress((void**)&x,  g_x);
    float* h  = nullptr; cudaGetSymbolAddress((void**)&h,  g_h);
    float* q  = nullptr; cudaGetSymbolAddress((void**)&q,  g_q);
    float* k  = nullptr; cudaGetSymbolAddress((void**)&k,  g_k);
    float* v  = nullptr; cudaGetSymbolAddress((void**)&v,  g_v);
    float* att= nullptr; cudaGetSymbolAddress((void**)&att,g_att);
    float* a  = nullptr; cudaGetSymbolAddress((void**)&a,  g_a);
    float* ff = nullptr; cudaGetSymbolAddress((void**)&ff, g_ff);
    float* rowloss = nullptr; cudaGetSymbolAddress((void**)&rowloss, g_rowloss);

    const float rs = rsqrtf((float)HS);

    embed_kernel<<<(BT * CC + 255) / 256, 256>>>(idx, tok_emb, pos_emb, x);

    for (int l = 0; l < LL; l++) {
        const float* wq = Wq + (size_t)l * CC * CC;
        const float* wk = Wk + (size_t)l * CC * CC;
        const float* wv = Wv + (size_t)l * CC * CC;
        const float* wp = Wproj + (size_t)l * CC * CC;
        const float* bp = bproj + (size_t)l * CC;
        const float* w1 = W1 + (size_t)l * CC * FFD;
        const float* bb1 = b1 + (size_t)l * FFD;
        const float* w2 = W2 + (size_t)l * FFD * CC;
        const float* bb2 = b2 + (size_t)l * CC;

        ln_kernel<<<BT, 256>>>(x, ln1_g + (size_t)l * CC, ln1_b + (size_t)l * CC, h);

        gemm_tc<false,false,false,false,true,false><<<ggrid(BT, CC, 1), 128>>>(h, wq, nullptr, q, BT, CC, CC, 1.f, 0, 0, 0);
        gemm_tc<false,false,false,false,true,false><<<ggrid(BT, CC, 1), 128>>>(h, wk, nullptr, k, BT, CC, CC, 1.f, 0, 0, 0);
        gemm_tc<false,false,false,false,true,false><<<ggrid(BT, CC, 1), 128>>>(h, wv, nullptr, v, BT, CC, CC, 1.f, 0, 0, 0);

        // scores = Q @ K^T * rs  (batched over B*H)
        gemm_tc<true,false,false,false,false,false><<<ggrid(TT, TT, BB * HH), 128>>>(
            q, k, nullptr, att, TT, TT, HS, rs,
            (size_t)TT * HS, (size_t)TT * HS, (size_t)TT * TT);

        softmax_kernel<<<BB * HH * TT / 8, 256>>>(att);

        // A = softmax @ V  (batched)
        gemm_tc<false,false,false,false,false,false><<<ggrid(TT, HS, BB * HH), 128>>>(
            att, v, nullptr, a, TT, HS, TT, 1.f,
            (size_t)TT * TT, (size_t)TT * HS, (size_t)TT * HS);

        // x += attn_out @ Wproj + bproj  (A gathered from [B,H,T,HS])
        gemm_tc<false,true,false,true,false,true><<<ggrid(BT, CC, 1), 128>>>(a, wp, bp, x, BT, CC, CC, 1.f, 0, 0, 0);

        ln_kernel<<<BT, 256>>>(x, ln2_g + (size_t)l * CC, ln2_b + (size_t)l * CC, h);

        // ff = relu(h @ W1 + b1)
        gemm_tc<false,true,true,false,false,false><<<ggrid(BT, FFD, 1), 128>>>(h, w1, bb1, ff, BT, FFD, CC, 1.f, 0, 0, 0);

        // x += ff @ W2 + b2
        gemm_tc<false,true,false,true,false,false><<<ggrid(BT, CC, 1), 128>>>(ff, w2, bb2, x, BT, CC, FFD, 1.f, 0, 0, 0);
    }

    ln_kernel<<<BT, 256>>>(x, lnf_g, lnf_b, h);

    // logits = h @ Wlm + blm
    gemm_tc<false,true,false,false,false,false><<<ggrid(BT, VV, 1), 128>>>(h, Wlm, blm, out, BT, VV, CC, 1.f, 0, 0, 0);

    rowloss_kernel<<<BT, 256>>>(out, targets, rowloss);
    if ((long long)out_size > (long long)BT * VV) {
        lossreduce_kernel<<<1, 256>>>(rowloss, out + (size_t)BT * VV);
    }
}

// round 8
// speedup vs baseline: 1.4832x; 1.4832x over previous
#include <cuda_runtime.h>
#include <cuda_fp16.h>
#include <math.h>
#include <stdint.h>

// ---------------- problem constants ----------------
constexpr int BB = 32, TT = 256, VV = 30522, CC = 768, HH = 8, LL = 10;
constexpr int HS = CC / HH;     // 96
constexpr int FFD = 4 * CC;     // 3072
constexpr int BT = BB * TT;     // 8192
constexpr float LN_EPS = 1e-5f;

// ---------------- scratch ----------------
__device__ float g_x[BT * CC];
__device__ float g_h[BT * CC];
__device__ float g_q[BT * CC];          // [B,H,T,HS]
__device__ float g_k[BT * CC];          // [B,H,T,HS]
__device__ float g_v[BT * CC];          // [B,H,T,HS]
__device__ float g_att[(size_t)BB * HH * TT * TT];
__device__ float g_a[BT * CC];          // [B,H,T,HS]
__device__ float g_ff[(size_t)BT * FFD];
__device__ float g_rowloss[BT];

// pack two floats into one half2 register (lo in low 16 bits)
__device__ __forceinline__ uint32_t f2h2(float lo, float hi) {
    uint32_t r;
    asm("{ .reg .f16 a, b; cvt.rn.f16.f32 a, %1; cvt.rn.f16.f32 b, %2; mov.b32 %0, {a, b}; }"
        : "=r"(r) : "f"(lo), "f"(hi));
    return r;
}

__device__ __forceinline__ void mma_fp16(float d[4], const uint32_t a[4], const uint32_t b[2]) {
    asm volatile(
        "mma.sync.aligned.m16n8k16.row.col.f32.f16.f16.f32 "
        "{%0,%1,%2,%3}, {%4,%5,%6,%7}, {%8,%9}, {%0,%1,%2,%3};\n"
        : "+f"(d[0]), "+f"(d[1]), "+f"(d[2]), "+f"(d[3])
        : "r"(a[0]), "r"(a[1]), "r"(a[2]), "r"(a[3]), "r"(b[0]), "r"(b[1]));
}

// ---------------- embedding ----------------
__global__ void embed_kernel(const int* __restrict__ idx,
                             const float* __restrict__ tok,
                             const float* __restrict__ pos,
                             float* __restrict__ x) {
    int i = blockIdx.x * blockDim.x + threadIdx.x;
    if (i >= BT * CC) return;
    int bt = i / CC, c = i % CC;
    int t = bt % TT;
    x[i] = tok[(size_t)idx[bt] * CC + c] + pos[(size_t)t * CC + c];
}

// ---------------- layernorm ----------------
__global__ void ln_kernel(const float* __restrict__ x,
                          const float* __restrict__ g,
                          const float* __restrict__ b,
                          float* __restrict__ out) {
    int row = blockIdx.x;
    const float* xr = x + (size_t)row * CC;
    float* orow = out + (size_t)row * CC;
    __shared__ float red[256];
    __shared__ float s_mu, s_inv;
    int tid = threadIdx.x;

    float s = 0.f;
    for (int c = tid; c < CC; c += 256) s += xr[c];
    red[tid] = s; __syncthreads();
    for (int st = 128; st > 0; st >>= 1) { if (tid < st) red[tid] += red[tid + st]; __syncthreads(); }
    if (tid == 0) s_mu = red[0] / CC;
    __syncthreads();
    float mu = s_mu;

    float v = 0.f;
    for (int c = tid; c < CC; c += 256) { float d = xr[c] - mu; v += d * d; }
    red[tid] = v; __syncthreads();
    for (int st = 128; st > 0; st >>= 1) { if (tid < st) red[tid] += red[tid + st]; __syncthreads(); }
    if (tid == 0) s_inv = rsqrtf(red[0] / CC + LN_EPS);
    __syncthreads();
    float inv = s_inv;

    for (int c = tid; c < CC; c += 256)
        orow[c] = (xr[c] - mu) * inv * g[c] + b[c];
}

// ---------------- fp16 tensor-core GEMM: 128x128x32, m16n8k16 ----------------
// C[M,N] = alpha * A @ B (+bias)(+relu)(+=C)
// TB:   B gmem [N,K] (A @ B^T)
// QKV:  scatter C into [B,H,T,HS];  AQKV: gather A from [B,H,T,HS]
// All call sites: M % 128 == 0, K % 32 == 0.
template<bool TB, bool BIAS, bool RELU, bool ACC, bool QKV, bool AQKV>
__global__ __launch_bounds__(256, 2)
void gemm_tc(const float* __restrict__ A, const float* __restrict__ Bm,
             const float* __restrict__ bias, float* __restrict__ Cm,
             int M, int N, int K, float alpha,
             size_t sA, size_t sB, size_t sC) {
    constexpr int BM = 128, BN = 128, BK = 32;
    constexpr int SA = 20;   // As2 row stride in words — frag-conflict-free
    constexpr int SBW = 136; // Bs2 row stride in words — frag-conflict-free
    __shared__ __align__(16) uint32_t As2[2][BM][SA];
    __shared__ __align__(16) uint32_t Bs2[2][BK / 2][SBW];

    const float* Ab = A + (size_t)blockIdx.z * sA;
    const float* Bb = Bm + (size_t)blockIdx.z * sB;
    float* Cb = Cm + (size_t)blockIdx.z * sC;

    int bm = blockIdx.y * BM;
    int bn = blockIdx.x * BN;
    int tid = threadIdx.x;
    int wid = tid >> 5, lane = tid & 31;
    int wm = (wid & 1) * 64;     // 2 warps along M
    int wn = (wid >> 1) * 32;    // 4 warps along N
    int gq = lane >> 2;          // 0..7
    int cq = lane & 3;           // 0..3

    // vector loads from B[K,N] only when fully in-range AND row stride keeps
    // 16B alignment (N % 4 == 0). LM head has N = 30522 (% 4 == 2) -> scalar.
    const bool bvec = (!TB) && (bn + BN <= N) && ((N & 3) == 0);

    float acc[4][4][4];
    #pragma unroll
    for (int i = 0; i < 4; i++)
        #pragma unroll
        for (int j = 0; j < 4; j++)
            #pragma unroll
            for (int t = 0; t < 4; t++) acc[i][j][t] = 0.f;

    uint32_t rA[8], rB[8];

    auto loadA = [&](int k0) {
        #pragma unroll
        for (int r = 0; r < 4; r++) {
            int id = tid + r * 256;            // 1024 float4 slots
            int m = id >> 3, kk4 = (id & 7) * 4;
            int row = bm + m, gk = k0 + kk4;
            const float* src;
            if (AQKV) {
                int b = row / TT, t = row % TT, h = gk / HS, d = gk % HS;
                src = &Ab[(((size_t)b * HH + h) * TT + t) * HS + d];
            } else {
                src = &Ab[(size_t)row * K + gk];
            }
            float4 v = *reinterpret_cast<const float4*>(src);
            rA[2 * r + 0] = f2h2(v.x, v.y);
            rA[2 * r + 1] = f2h2(v.z, v.w);
        }
    };
    auto storeA = [&](int buf) {
        #pragma unroll
        for (int r = 0; r < 4; r++) {
            int id = tid + r * 256;
            int m = id >> 3, k2 = (id & 7) * 2;
            As2[buf][m][k2 + 0] = rA[2 * r + 0];
            As2[buf][m][k2 + 1] = rA[2 * r + 1];
        }
    };
    auto loadB = [&](int k0) {
        if (!TB) {
            // B [K,N]: each slot covers (k-pair, 4 n)
            #pragma unroll
            for (int r = 0; r < 2; r++) {
                int id = tid + r * 256;          // 512 slots
                int k2 = id >> 5;                // 0..15
                int n4 = (id & 31) * 4;          // 0..124
                int gk = k0 + 2 * k2;
                int gn = bn + n4;
                float4 v0, v1;
                if (bvec) {
                    v0 = *reinterpret_cast<const float4*>(&Bb[(size_t)gk * N + gn]);
                    v1 = *reinterpret_cast<const float4*>(&Bb[(size_t)(gk + 1) * N + gn]);
                } else {
                    float t0[4], t1[4];
                    #pragma unroll
                    for (int j = 0; j < 4; j++) {
                        int g = gn + j;
                        t0[j] = (g < N) ? Bb[(size_t)gk * N + g] : 0.f;
                        t1[j] = (g < N) ? Bb[(size_t)(gk + 1) * N + g] : 0.f;
                    }
                    v0 = make_float4(t0[0], t0[1], t0[2], t0[3]);
                    v1 = make_float4(t1[0], t1[1], t1[2], t1[3]);
                }
                rB[r * 4 + 0] = f2h2(v0.x, v1.x);
                rB[r * 4 + 1] = f2h2(v0.y, v1.y);
                rB[r * 4 + 2] = f2h2(v0.z, v1.z);
                rB[r * 4 + 3] = f2h2(v0.w, v1.w);
            }
        } else {
            // B [N,K]: each slot covers (n, 4 k); K % 4 == 0 at all call sites
            #pragma unroll
            for (int r = 0; r < 4; r++) {
                int id = tid + r * 256;          // 1024 slots
                int n = id >> 3, kk4 = (id & 7) * 4;
                int gn = bn + n;
                float4 v;
                if (gn < N) {
                    v = *reinterpret_cast<const float4*>(&Bb[(size_t)gn * K + k0 + kk4]);
                } else {
                    v = make_float4(0.f, 0.f, 0.f, 0.f);
                }
                rB[2 * r + 0] = f2h2(v.x, v.y);
                rB[2 * r + 1] = f2h2(v.z, v.w);
            }
        }
    };
    auto storeB = [&](int buf) {
        if (!TB) {
            #pragma unroll
            for (int r = 0; r < 2; r++) {
                int id = tid + r * 256;
                int k2 = id >> 5;
                int n4 = (id & 31) * 4;
                uint4 v = make_uint4(rB[r * 4 + 0], rB[r * 4 + 1], rB[r * 4 + 2], rB[r * 4 + 3]);
                *reinterpret_cast<uint4*>(&Bs2[buf][k2][n4]) = v;
            }
        } else {
            #pragma unroll
            for (int r = 0; r < 4; r++) {
                int id = tid + r * 256;
                int n = id >> 3, k2 = (id & 7) * 2;
                Bs2[buf][k2 + 0][n] = rB[2 * r + 0];
                Bs2[buf][k2 + 1][n] = rB[2 * r + 1];
            }
        }
    };

    // prologue
    loadA(0); loadB(0);
    storeA(0); storeB(0);
    __syncthreads();

    int cur = 0;
    for (int k0 = 0; k0 < K; k0 += BK) {
        bool has_next = (k0 + BK) < K;
        if (has_next) { loadA(k0 + BK); loadB(k0 + BK); }

        #pragma unroll
        for (int kk2 = 0; kk2 < BK / 2; kk2 += 8) {     // two k16-steps
            uint32_t af[4][4];
            uint32_t bf[4][2];
            #pragma unroll
            for (int i = 0; i < 4; i++) {
                int mr = wm + i * 16;
                af[i][0] = As2[cur][mr + gq][kk2 + cq];
                af[i][1] = As2[cur][mr + gq + 8][kk2 + cq];
                af[i][2] = As2[cur][mr + gq][kk2 + cq + 4];
                af[i][3] = As2[cur][mr + gq + 8][kk2 + cq + 4];
            }
            #pragma unroll
            for (int j = 0; j < 4; j++) {
                int nc = wn + j * 8 + gq;
                bf[j][0] = Bs2[cur][kk2 + cq][nc];
                bf[j][1] = Bs2[cur][kk2 + cq + 4][nc];
            }
            #pragma unroll
            for (int i = 0; i < 4; i++)
                #pragma unroll
                for (int j = 0; j < 4; j++)
                    mma_fp16(acc[i][j], af[i], bf[j]);
        }

        if (has_next) { storeA(cur ^ 1); storeB(cur ^ 1); }
        __syncthreads();
        cur ^= 1;
    }

    // epilogue
    #pragma unroll
    for (int i = 0; i < 4; i++) {
        int r0 = bm + wm + i * 16 + gq;
        #pragma unroll
        for (int j = 0; j < 4; j++) {
            int c0 = bn + wn + j * 8 + cq * 2;
            if (c0 >= N) continue;
            #pragma unroll
            for (int half = 0; half < 2; half++) {
                int row = r0 + half * 8;
                float v0 = acc[i][j][half * 2 + 0] * alpha;
                float v1 = acc[i][j][half * 2 + 1] * alpha;
                if (BIAS) { v0 += bias[c0]; v1 += (c0 + 1 < N) ? bias[c0 + 1] : 0.f; }
                if (RELU) { v0 = fmaxf(v0, 0.f); v1 = fmaxf(v1, 0.f); }
                size_t oidx;
                if (QKV) {
                    int b = row / TT, t = row % TT, h = c0 / HS, d = c0 % HS;
                    oidx = (((size_t)b * HH + h) * TT + t) * HS + d;
                } else {
                    oidx = (size_t)row * N + c0;
                }
                if (c0 + 1 < N) {
                    if (ACC) {
                        float2 old = *reinterpret_cast<float2*>(&Cb[oidx]);
                        v0 += old.x; v1 += old.y;
                    }
                    *reinterpret_cast<float2*>(&Cb[oidx]) = make_float2(v0, v1);
                } else {
                    if (ACC) v0 += Cb[oidx];
                    Cb[oidx] = v0;
                }
            }
        }
    }
}

// ---------------- causal softmax: one warp per row ----------------
__global__ void softmax_kernel(float* __restrict__ att) {
    int warp = threadIdx.x >> 5, lane = threadIdx.x & 31;
    size_t row = (size_t)blockIdx.x * 8 + warp;
    int qi = (int)(row % TT);
    float* w = att + row * (size_t)TT;

    int i0 = lane * 4, i1 = 128 + lane * 4;
    float4 a0 = *reinterpret_cast<float4*>(&w[i0]);
    float4 a1 = *reinterpret_cast<float4*>(&w[i1]);
    float v[8] = {a0.x, a0.y, a0.z, a0.w, a1.x, a1.y, a1.z, a1.w};
    int base[2] = {i0, i1};

    float mx = -1e30f;
    #pragma unroll
    for (int h = 0; h < 2; h++)
        #pragma unroll
        for (int j = 0; j < 4; j++)
            if (base[h] + j <= qi) mx = fmaxf(mx, v[h * 4 + j]);
    #pragma unroll
    for (int s = 16; s > 0; s >>= 1) mx = fmaxf(mx, __shfl_xor_sync(0xffffffffu, mx, s));

    float e[8];
    float sum = 0.f;
    #pragma unroll
    for (int h = 0; h < 2; h++)
        #pragma unroll
        for (int j = 0; j < 4; j++) {
            int idx = h * 4 + j;
            e[idx] = (base[h] + j <= qi) ? expf(v[idx] - mx) : 0.f;
            sum += e[idx];
        }
    #pragma unroll
    for (int s = 16; s > 0; s >>= 1) sum += __shfl_xor_sync(0xffffffffu, sum, s);
    float inv = 1.f / sum;

    *reinterpret_cast<float4*>(&w[i0]) = make_float4(e[0] * inv, e[1] * inv, e[2] * inv, e[3] * inv);
    *reinterpret_cast<float4*>(&w[i1]) = make_float4(e[4] * inv, e[5] * inv, e[6] * inv, e[7] * inv);
}

// ---------------- loss ----------------
__global__ void rowloss_kernel(const float* __restrict__ logits,
                               const int* __restrict__ targets,
                               float* __restrict__ rowloss) {
    int r = blockIdx.x;
    const float* lr = logits + (size_t)r * VV;
    int tid = threadIdx.x;
    __shared__ float red[256];
    __shared__ float s_mx;

    float mx = -1e30f;
    for (int c = tid; c < VV; c += 256) mx = fmaxf(mx, lr[c]);
    red[tid] = mx; __syncthreads();
    for (int st = 128; st > 0; st >>= 1) { if (tid < st) red[tid] = fmaxf(red[tid], red[tid + st]); __syncthreads(); }
    if (tid == 0) s_mx = red[0];
    __syncthreads();
    mx = s_mx;

    float s = 0.f;
    for (int c = tid; c < VV; c += 256) s += expf(lr[c] - mx);
    red[tid] = s; __syncthreads();
    for (int st = 128; st > 0; st >>= 1) { if (tid < st) red[tid] += red[tid + st]; __syncthreads(); }
    if (tid == 0) {
        int t = targets[r];
        rowloss[r] = -(lr[t] - mx - logf(red[0]));
    }
}

__global__ void lossreduce_kernel(const float* __restrict__ rowloss, float* __restrict__ out) {
    __shared__ float red[256];
    int tid = threadIdx.x;
    float s = 0.f;
    for (int r = tid; r < BT; r += 256) s += rowloss[r];
    red[tid] = s; __syncthreads();
    for (int st = 128; st > 0; st >>= 1) { if (tid < st) red[tid] += red[tid + st]; __syncthreads(); }
    if (tid == 0) out[0] = red[0] / BT;
}

// ---------------- host ----------------
static inline dim3 ggrid(int M, int N, int batch) {
    return dim3((N + 127) / 128, (M + 127) / 128, batch);
}

extern "C" void kernel_launch(void* const* d_in, const int* in_sizes, int n_in,
                              void* d_out, int out_size) {
    const int*   idx     = (const int*)  d_in[0];
    const int*   targets = (const int*)  d_in[1];
    const float* tok_emb = (const float*)d_in[2];
    const float* pos_emb = (const float*)d_in[3];
    const float* Wq      = (const float*)d_in[4];
    const float* Wk      = (const float*)d_in[5];
    const float* Wv      = (const float*)d_in[6];
    const float* Wproj   = (const float*)d_in[7];
    const float* bproj   = (const float*)d_in[8];
    const float* W1      = (const float*)d_in[9];
    const float* b1      = (const float*)d_in[10];
    const float* W2      = (const float*)d_in[11];
    const float* b2      = (const float*)d_in[12];
    const float* ln1_g   = (const float*)d_in[13];
    const float* ln1_b   = (const float*)d_in[14];
    const float* ln2_g   = (const float*)d_in[15];
    const float* ln2_b   = (const float*)d_in[16];
    const float* lnf_g   = (const float*)d_in[17];
    const float* lnf_b   = (const float*)d_in[18];
    const float* Wlm     = (const float*)d_in[19];
    const float* blm     = (const float*)d_in[20];
    float* out = (float*)d_out;

    float* x  = nullptr; cudaGetSymbolAddress((void**)&x,  g_x);
    float* h  = nullptr; cudaGetSymbolAddress((void**)&h,  g_h);
    float* q  = nullptr; cudaGetSymbolAddress((void**)&q,  g_q);
    float* k  = nullptr; cudaGetSymbolAddress((void**)&k,  g_k);
    float* v  = nullptr; cudaGetSymbolAddress((void**)&v,  g_v);
    float* att= nullptr; cudaGetSymbolAddress((void**)&att,g_att);
    float* a  = nullptr; cudaGetSymbolAddress((void**)&a,  g_a);
    float* ff = nullptr; cudaGetSymbolAddress((void**)&ff, g_ff);
    float* rowloss = nullptr; cudaGetSymbolAddress((void**)&rowloss, g_rowloss);

    const float rs = rsqrtf((float)HS);

    embed_kernel<<<(BT * CC + 255) / 256, 256>>>(idx, tok_emb, pos_emb, x);

    for (int l = 0; l < LL; l++) {
        const float* wq = Wq + (size_t)l * CC * CC;
        const float* wk = Wk + (size_t)l * CC * CC;
        const float* wv = Wv + (size_t)l * CC * CC;
        const float* wp = Wproj + (size_t)l * CC * CC;
        const float* bp = bproj + (size_t)l * CC;
        const float* w1 = W1 + (size_t)l * CC * FFD;
        const float* bb1 = b1 + (size_t)l * FFD;
        const float* w2 = W2 + (size_t)l * FFD * CC;
        const float* bb2 = b2 + (size_t)l * CC;

        ln_kernel<<<BT, 256>>>(x, ln1_g + (size_t)l * CC, ln1_b + (size_t)l * CC, h);

        gemm_tc<false,false,false,false,true,false><<<ggrid(BT, CC, 1), 256>>>(h, wq, nullptr, q, BT, CC, CC, 1.f, 0, 0, 0);
        gemm_tc<false,false,false,false,true,false><<<ggrid(BT, CC, 1), 256>>>(h, wk, nullptr, k, BT, CC, CC, 1.f, 0, 0, 0);
        gemm_tc<false,false,false,false,true,false><<<ggrid(BT, CC, 1), 256>>>(h, wv, nullptr, v, BT, CC, CC, 1.f, 0, 0, 0);

        // scores = Q @ K^T * rs  (batched over B*H); K=HS=96
        gemm_tc<true,false,false,false,false,false><<<ggrid(TT, TT, BB * HH), 256>>>(
            q, k, nullptr, att, TT, TT, HS, rs,
            (size_t)TT * HS, (size_t)TT * HS, (size_t)TT * TT);

        softmax_kernel<<<BB * HH * TT / 8, 256>>>(att);

        // A = softmax @ V  (batched)
        gemm_tc<false,false,false,false,false,false><<<ggrid(TT, HS, BB * HH), 256>>>(
            att, v, nullptr, a, TT, HS, TT, 1.f,
            (size_t)TT * TT, (size_t)TT * HS, (size_t)TT * HS);

        // x += attn_out @ Wproj + bproj  (A gathered from [B,H,T,HS])
        gemm_tc<false,true,false,true,false,true><<<ggrid(BT, CC, 1), 256>>>(a, wp, bp, x, BT, CC, CC, 1.f, 0, 0, 0);

        ln_kernel<<<BT, 256>>>(x, ln2_g + (size_t)l * CC, ln2_b + (size_t)l * CC, h);

        // ff = relu(h @ W1 + b1)
        gemm_tc<false,true,true,false,false,false><<<ggrid(BT, FFD, 1), 256>>>(h, w1, bb1, ff, BT, FFD, CC, 1.f, 0, 0, 0);

        // x += ff @ W2 + b2
        gemm_tc<false,true,false,true,false,false><<<ggrid(BT, CC, 1), 256>>>(ff, w2, bb2, x, BT, CC, FFD, 1.f, 0, 0, 0);
    }

    ln_kernel<<<BT, 256>>>(x, lnf_g, lnf_b, h);

    // logits = h @ Wlm + blm   (N = 30522, N % 4 != 0 -> scalar B loads)
    gemm_tc<false,true,false,false,false,false><<<ggrid(BT, VV, 1), 256>>>(h, Wlm, blm, out, BT, VV, CC, 1.f, 0, 0, 0);

    rowloss_kernel<<<BT, 256>>>(out, targets, rowloss);
    if ((long long)out_size > (long long)BT * VV) {
        lossreduce_kernel<<<1, 256>>>(rowloss, out + (size_t)BT * VV);
    }
}

// round 9
// speedup vs baseline: 1.9132x; 1.2899x over previous
#include <cuda_runtime.h>
#include <cuda_fp16.h>
#include <math.h>
#include <stdint.h>

// ---------------- problem constants ----------------
constexpr int BB = 32, TT = 256, VV = 30522, CC = 768, HH = 8, LL = 10;
constexpr int HS = CC / HH;     // 96
constexpr int FFD = 4 * CC;     // 3072
constexpr int BT = BB * TT;     // 8192
constexpr int VVP = 30592;      // VV padded to 239*128
constexpr float LN_EPS = 1e-5f;

// ---------------- scratch ----------------
__device__ float g_x[BT * CC];
__device__ float g_h[BT * CC];
__device__ float g_qkv[3 * BT * CC];           // q|k|v each [B,H,T,HS]
__device__ float g_att[(size_t)BB * HH * TT * TT];
__device__ float g_a[BT * CC];                 // [B,H,T,HS]
__device__ float g_ff[(size_t)BT * FFD];
__device__ float g_rowloss[BT];
// pre-packed fp16 weights: [K/2][N] uint32 = half2(W[2k2][n], W[2k2+1][n])
__device__ uint32_t g_wqkv16[(size_t)LL * (CC / 2) * (3 * CC)];
__device__ uint32_t g_wproj16[(size_t)LL * (CC / 2) * CC];
__device__ uint32_t g_w116[(size_t)LL * (CC / 2) * FFD];
__device__ uint32_t g_w216[(size_t)LL * (FFD / 2) * CC];
__device__ uint32_t g_wlm16[(size_t)(CC / 2) * VVP];

// pack two floats into one half2 register (lo in low 16 bits)
__device__ __forceinline__ uint32_t f2h2(float lo, float hi) {
    uint32_t r;
    asm("{ .reg .f16 a, b; cvt.rn.f16.f32 a, %1; cvt.rn.f16.f32 b, %2; mov.b32 %0, {a, b}; }"
        : "=r"(r) : "f"(lo), "f"(hi));
    return r;
}

__device__ __forceinline__ void mma_fp16(float d[4], const uint32_t a[4], const uint32_t b[2]) {
    asm volatile(
        "mma.sync.aligned.m16n8k16.row.col.f32.f16.f16.f32 "
        "{%0,%1,%2,%3}, {%4,%5,%6,%7}, {%8,%9}, {%0,%1,%2,%3};\n"
        : "+f"(d[0]), "+f"(d[1]), "+f"(d[2]), "+f"(d[3])
        : "r"(a[0]), "r"(a[1]), "r"(a[2]), "r"(a[3]), "r"(b[0]), "r"(b[1]));
}

// ---------------- weight packing ----------------
// out[k2*Nb + n] = half2(W[(2k2)*N+n], W[(2k2+1)*N+n]); zero-pad n >= N.
// Works for layer-stacked W when K per layer is even (pairs never cross layers).
__global__ void pack_w_kernel(const float* __restrict__ W, uint32_t* __restrict__ out,
                              int K2tot, int N, int Nb) {
    size_t i = (size_t)blockIdx.x * blockDim.x + threadIdx.x;
    if (i >= (size_t)K2tot * Nb) return;
    int k2 = (int)(i / Nb), n = (int)(i % Nb);
    float lo = 0.f, hi = 0.f;
    if (n < N) {
        lo = W[(size_t)(2 * k2) * N + n];
        hi = W[(size_t)(2 * k2 + 1) * N + n];
    }
    out[i] = f2h2(lo, hi);
}

// fused QKV pack: out[l][k2][n], n in [0,3C): 0..C-1 from Wq, C..2C-1 Wk, rest Wv
__global__ void pack_qkv_kernel(const float* __restrict__ Wq, const float* __restrict__ Wk,
                                const float* __restrict__ Wv, uint32_t* __restrict__ out) {
    size_t i = (size_t)blockIdx.x * blockDim.x + threadIdx.x;
    const size_t total = (size_t)LL * (CC / 2) * (3 * CC);
    if (i >= total) return;
    int n = (int)(i % (3 * CC));
    size_t rest = i / (3 * CC);
    int k2 = (int)(rest % (CC / 2));
    int l = (int)(rest / (CC / 2));
    int which = n / CC, nn = n % CC;
    const float* W = (which == 0) ? Wq : (which == 1) ? Wk : Wv;
    const float* base = W + (size_t)l * CC * CC;
    out[i] = f2h2(base[(size_t)(2 * k2) * CC + nn], base[(size_t)(2 * k2 + 1) * CC + nn]);
}

// ---------------- embedding ----------------
__global__ void embed_kernel(const int* __restrict__ idx,
                             const float* __restrict__ tok,
                             const float* __restrict__ pos,
                             float* __restrict__ x) {
    int i = blockIdx.x * blockDim.x + threadIdx.x;
    if (i >= BT * CC) return;
    int bt = i / CC, c = i % CC;
    int t = bt % TT;
    x[i] = tok[(size_t)idx[bt] * CC + c] + pos[(size_t)t * CC + c];
}

// ---------------- layernorm ----------------
__global__ void ln_kernel(const float* __restrict__ x,
                          const float* __restrict__ g,
                          const float* __restrict__ b,
                          float* __restrict__ out) {
    int row = blockIdx.x;
    const float* xr = x + (size_t)row * CC;
    float* orow = out + (size_t)row * CC;
    __shared__ float red[256];
    __shared__ float s_mu, s_inv;
    int tid = threadIdx.x;

    float s = 0.f;
    for (int c = tid; c < CC; c += 256) s += xr[c];
    red[tid] = s; __syncthreads();
    for (int st = 128; st > 0; st >>= 1) { if (tid < st) red[tid] += red[tid + st]; __syncthreads(); }
    if (tid == 0) s_mu = red[0] / CC;
    __syncthreads();
    float mu = s_mu;

    float v = 0.f;
    for (int c = tid; c < CC; c += 256) { float d = xr[c] - mu; v += d * d; }
    red[tid] = v; __syncthreads();
    for (int st = 128; st > 0; st >>= 1) { if (tid < st) red[tid] += red[tid + st]; __syncthreads(); }
    if (tid == 0) s_inv = rsqrtf(red[0] / CC + LN_EPS);
    __syncthreads();
    float inv = s_inv;

    for (int c = tid; c < CC; c += 256)
        orow[c] = (xr[c] - mu) * inv * g[c] + b[c];
}

// ---------------- fp16 tensor-core GEMM: 128x128x32, m16n8k16 ----------------
// C[M,N] = alpha * A @ B (+bias)(+relu)(+=C)
// BPK:  B is pre-packed half2-paired uint32 [K/2][Nb] (requires grid covers Nb)
// TB:   B gmem [N,K] f32 (A @ B^T)
// QKV:  scatter C: col c -> tensor (c/CC) at [B,H,T,HS] (Cb = qkv base)
// AQKV: gather A from [B,H,T,HS]
// All call sites: M % 128 == 0, K % 32 == 0.
template<bool BPK, bool TB, bool BIAS, bool RELU, bool ACC, bool QKV, bool AQKV>
__global__ __launch_bounds__(256, 2)
void gemm_tc(const float* __restrict__ A, const void* __restrict__ Bmv,
             const float* __restrict__ bias, float* __restrict__ Cm,
             int M, int N, int Nb, int K, float alpha,
             size_t sA, size_t sB, size_t sC) {
    constexpr int BM = 128, BN = 128, BK = 32;
    constexpr int SA = 20;
    constexpr int SBW = 136;
    __shared__ __align__(16) uint32_t As2[2][BM][SA];
    __shared__ __align__(16) uint32_t Bs2[2][BK / 2][SBW];

    const float* Ab = A + (size_t)blockIdx.z * sA;
    const float* Bb = (const float*)Bmv + (BPK ? 0 : (size_t)blockIdx.z * sB);
    const uint32_t* Bw = (const uint32_t*)Bmv;
    float* Cb = Cm + (size_t)blockIdx.z * sC;

    int bm = blockIdx.y * BM;
    int bn = blockIdx.x * BN;
    int tid = threadIdx.x;
    int wid = tid >> 5, lane = tid & 31;
    int wm = (wid & 1) * 64;
    int wn = (wid >> 1) * 32;
    int gq = lane >> 2;
    int cq = lane & 3;

    const bool bvecN = (!TB) && ((N & 3) == 0);

    float acc[4][4][4];
    #pragma unroll
    for (int i = 0; i < 4; i++)
        #pragma unroll
        for (int j = 0; j < 4; j++)
            #pragma unroll
            for (int t = 0; t < 4; t++) acc[i][j][t] = 0.f;

    uint32_t rA[8], rB[8];

    auto loadA = [&](int k0) {
        #pragma unroll
        for (int r = 0; r < 4; r++) {
            int id = tid + r * 256;
            int m = id >> 3, kk4 = (id & 7) * 4;
            int row = bm + m, gk = k0 + kk4;
            const float* src;
            if (AQKV) {
                int b = row / TT, t = row % TT, h = gk / HS, d = gk % HS;
                src = &Ab[(((size_t)b * HH + h) * TT + t) * HS + d];
            } else {
                src = &Ab[(size_t)row * K + gk];
            }
            float4 v = *reinterpret_cast<const float4*>(src);
            rA[2 * r + 0] = f2h2(v.x, v.y);
            rA[2 * r + 1] = f2h2(v.z, v.w);
        }
    };
    auto storeA = [&](int buf) {
        #pragma unroll
        for (int r = 0; r < 4; r++) {
            int id = tid + r * 256;
            int m = id >> 3, k2 = (id & 7) * 2;
            As2[buf][m][k2 + 0] = rA[2 * r + 0];
            As2[buf][m][k2 + 1] = rA[2 * r + 1];
        }
    };
    auto loadB = [&](int k0) {
        if (BPK) {
            // pre-packed [K/2][Nb]: one uint4 = 4 paired words (8 halves over 4 n)
            #pragma unroll
            for (int r = 0; r < 2; r++) {
                int id = tid + r * 256;
                int k2 = id >> 5;                // 0..15
                int n4 = (id & 31) * 4;
                const uint4 v = *reinterpret_cast<const uint4*>(
                    &Bw[(size_t)(k0 / 2 + k2) * Nb + bn + n4]);
                rB[r * 4 + 0] = v.x; rB[r * 4 + 1] = v.y;
                rB[r * 4 + 2] = v.z; rB[r * 4 + 3] = v.w;
            }
        } else if (!TB) {
            #pragma unroll
            for (int r = 0; r < 2; r++) {
                int id = tid + r * 256;
                int k2 = id >> 5;
                int n4 = (id & 31) * 4;
                int gk = k0 + 2 * k2;
                int gn = bn + n4;
                float4 v0, v1;
                if (bvecN && (gn + 3 < N)) {
                    v0 = *reinterpret_cast<const float4*>(&Bb[(size_t)gk * N + gn]);
                    v1 = *reinterpret_cast<const float4*>(&Bb[(size_t)(gk + 1) * N + gn]);
                } else {
                    float t0[4], t1[4];
                    #pragma unroll
                    for (int j = 0; j < 4; j++) {
                        int g = gn + j;
                        t0[j] = (g < N) ? Bb[(size_t)gk * N + g] : 0.f;
                        t1[j] = (g < N) ? Bb[(size_t)(gk + 1) * N + g] : 0.f;
                    }
                    v0 = make_float4(t0[0], t0[1], t0[2], t0[3]);
                    v1 = make_float4(t1[0], t1[1], t1[2], t1[3]);
                }
                rB[r * 4 + 0] = f2h2(v0.x, v1.x);
                rB[r * 4 + 1] = f2h2(v0.y, v1.y);
                rB[r * 4 + 2] = f2h2(v0.z, v1.z);
                rB[r * 4 + 3] = f2h2(v0.w, v1.w);
            }
        } else {
            #pragma unroll
            for (int r = 0; r < 4; r++) {
                int id = tid + r * 256;
                int n = id >> 3, kk4 = (id & 7) * 4;
                int gn = bn + n;
                float4 v;
                if (gn < N) {
                    v = *reinterpret_cast<const float4*>(&Bb[(size_t)gn * K + k0 + kk4]);
                } else {
                    v = make_float4(0.f, 0.f, 0.f, 0.f);
                }
                rB[2 * r + 0] = f2h2(v.x, v.y);
                rB[2 * r + 1] = f2h2(v.z, v.w);
            }
        }
    };
    auto storeB = [&](int buf) {
        if (BPK || !TB) {
            #pragma unroll
            for (int r = 0; r < 2; r++) {
                int id = tid + r * 256;
                int k2 = id >> 5;
                int n4 = (id & 31) * 4;
                uint4 v = make_uint4(rB[r * 4 + 0], rB[r * 4 + 1], rB[r * 4 + 2], rB[r * 4 + 3]);
                *reinterpret_cast<uint4*>(&Bs2[buf][k2][n4]) = v;
            }
        } else {
            #pragma unroll
            for (int r = 0; r < 4; r++) {
                int id = tid + r * 256;
                int n = id >> 3, k2 = (id & 7) * 2;
                Bs2[buf][k2 + 0][n] = rB[2 * r + 0];
                Bs2[buf][k2 + 1][n] = rB[2 * r + 1];
            }
        }
    };

    // prologue
    loadA(0); loadB(0);
    storeA(0); storeB(0);
    __syncthreads();

    int cur = 0;
    for (int k0 = 0; k0 < K; k0 += BK) {
        bool has_next = (k0 + BK) < K;
        if (has_next) { loadA(k0 + BK); loadB(k0 + BK); }

        #pragma unroll
        for (int kk2 = 0; kk2 < BK / 2; kk2 += 8) {
            uint32_t af[4][4];
            uint32_t bf[4][2];
            #pragma unroll
            for (int i = 0; i < 4; i++) {
                int mr = wm + i * 16;
                af[i][0] = As2[cur][mr + gq][kk2 + cq];
                af[i][1] = As2[cur][mr + gq + 8][kk2 + cq];
                af[i][2] = As2[cur][mr + gq][kk2 + cq + 4];
                af[i][3] = As2[cur][mr + gq + 8][kk2 + cq + 4];
            }
            #pragma unroll
            for (int j = 0; j < 4; j++) {
                int nc = wn + j * 8 + gq;
                bf[j][0] = Bs2[cur][kk2 + cq][nc];
                bf[j][1] = Bs2[cur][kk2 + cq + 4][nc];
            }
            #pragma unroll
            for (int i = 0; i < 4; i++)
                #pragma unroll
                for (int j = 0; j < 4; j++)
                    mma_fp16(acc[i][j], af[i], bf[j]);
        }

        if (has_next) { storeA(cur ^ 1); storeB(cur ^ 1); }
        __syncthreads();
        cur ^= 1;
    }

    // epilogue
    #pragma unroll
    for (int i = 0; i < 4; i++) {
        int r0 = bm + wm + i * 16 + gq;
        #pragma unroll
        for (int j = 0; j < 4; j++) {
            int c0 = bn + wn + j * 8 + cq * 2;
            if (c0 >= N) continue;
            #pragma unroll
            for (int half = 0; half < 2; half++) {
                int row = r0 + half * 8;
                float v0 = acc[i][j][half * 2 + 0] * alpha;
                float v1 = acc[i][j][half * 2 + 1] * alpha;
                if (BIAS) { v0 += bias[c0]; v1 += (c0 + 1 < N) ? bias[c0 + 1] : 0.f; }
                if (RELU) { v0 = fmaxf(v0, 0.f); v1 = fmaxf(v1, 0.f); }
                size_t oidx;
                if (QKV) {
                    int which = c0 / CC, cc = c0 % CC;
                    int b = row / TT, t = row % TT, h = cc / HS, d = cc % HS;
                    oidx = (size_t)which * BT * CC
                         + (((size_t)b * HH + h) * TT + t) * HS + d;
                } else {
                    oidx = (size_t)row * N + c0;
                }
                if (c0 + 1 < N) {
                    if (ACC) {
                        float2 old = *reinterpret_cast<float2*>(&Cb[oidx]);
                        v0 += old.x; v1 += old.y;
                    }
                    *reinterpret_cast<float2*>(&Cb[oidx]) = make_float2(v0, v1);
                } else {
                    if (ACC) v0 += Cb[oidx];
                    Cb[oidx] = v0;
                }
            }
        }
    }
}

// ---------------- causal softmax: one warp per row ----------------
__global__ void softmax_kernel(float* __restrict__ att) {
    int warp = threadIdx.x >> 5, lane = threadIdx.x & 31;
    size_t row = (size_t)blockIdx.x * 8 + warp;
    int qi = (int)(row % TT);
    float* w = att + row * (size_t)TT;

    int i0 = lane * 4, i1 = 128 + lane * 4;
    float4 a0 = *reinterpret_cast<float4*>(&w[i0]);
    float4 a1 = *reinterpret_cast<float4*>(&w[i1]);
    float v[8] = {a0.x, a0.y, a0.z, a0.w, a1.x, a1.y, a1.z, a1.w};
    int base[2] = {i0, i1};

    float mx = -1e30f;
    #pragma unroll
    for (int h = 0; h < 2; h++)
        #pragma unroll
        for (int j = 0; j < 4; j++)
            if (base[h] + j <= qi) mx = fmaxf(mx, v[h * 4 + j]);
    #pragma unroll
    for (int s = 16; s > 0; s >>= 1) mx = fmaxf(mx, __shfl_xor_sync(0xffffffffu, mx, s));

    float e[8];
    float sum = 0.f;
    #pragma unroll
    for (int h = 0; h < 2; h++)
        #pragma unroll
        for (int j = 0; j < 4; j++) {
            int idx = h * 4 + j;
            e[idx] = (base[h] + j <= qi) ? expf(v[idx] - mx) : 0.f;
            sum += e[idx];
        }
    #pragma unroll
    for (int s = 16; s > 0; s >>= 1) sum += __shfl_xor_sync(0xffffffffu, sum, s);
    float inv = 1.f / sum;

    *reinterpret_cast<float4*>(&w[i0]) = make_float4(e[0] * inv, e[1] * inv, e[2] * inv, e[3] * inv);
    *reinterpret_cast<float4*>(&w[i1]) = make_float4(e[4] * inv, e[5] * inv, e[6] * inv, e[7] * inv);
}

// ---------------- loss ----------------
__global__ void rowloss_kernel(const float* __restrict__ logits,
                               const int* __restrict__ targets,
                               float* __restrict__ rowloss) {
    int r = blockIdx.x;
    const float* lr = logits + (size_t)r * VV;
    int tid = threadIdx.x;
    __shared__ float red[256];
    __shared__ float s_mx;

    float mx = -1e30f;
    for (int c = tid; c < VV; c += 256) mx = fmaxf(mx, lr[c]);
    red[tid] = mx; __syncthreads();
    for (int st = 128; st > 0; st >>= 1) { if (tid < st) red[tid] = fmaxf(red[tid], red[tid + st]); __syncthreads(); }
    if (tid == 0) s_mx = red[0];
    __syncthreads();
    mx = s_mx;

    float s = 0.f;
    for (int c = tid; c < VV; c += 256) s += expf(lr[c] - mx);
    red[tid] = s; __syncthreads();
    for (int st = 128; st > 0; st >>= 1) { if (tid < st) red[tid] += red[tid + st]; __syncthreads(); }
    if (tid == 0) {
        int t = targets[r];
        rowloss[r] = -(lr[t] - mx - logf(red[0]));
    }
}

__global__ void lossreduce_kernel(const float* __restrict__ rowloss, float* __restrict__ out) {
    __shared__ float red[256];
    int tid = threadIdx.x;
    float s = 0.f;
    for (int r = tid; r < BT; r += 256) s += rowloss[r];
    red[tid] = s; __syncthreads();
    for (int st = 128; st > 0; st >>= 1) { if (tid < st) red[tid] += red[tid + st]; __syncthreads(); }
    if (tid == 0) out[0] = red[0] / BT;
}

// ---------------- host ----------------
static inline dim3 ggrid(int M, int N, int batch) {
    return dim3((N + 127) / 128, (M + 127) / 128, batch);
}

extern "C" void kernel_launch(void* const* d_in, const int* in_sizes, int n_in,
                              void* d_out, int out_size) {
    const int*   idx     = (const int*)  d_in[0];
    const int*   targets = (const int*)  d_in[1];
    const float* tok_emb = (const float*)d_in[2];
    const float* pos_emb = (const float*)d_in[3];
    const float* Wq      = (const float*)d_in[4];
    const float* Wk      = (const float*)d_in[5];
    const float* Wv      = (const float*)d_in[6];
    const float* Wproj   = (const float*)d_in[7];
    const float* bproj   = (const float*)d_in[8];
    const float* W1      = (const float*)d_in[9];
    const float* b1      = (const float*)d_in[10];
    const float* W2      = (const float*)d_in[11];
    const float* b2      = (const float*)d_in[12];
    const float* ln1_g   = (const float*)d_in[13];
    const float* ln1_b   = (const float*)d_in[14];
    const float* ln2_g   = (const float*)d_in[15];
    const float* ln2_b   = (const float*)d_in[16];
    const float* lnf_g   = (const float*)d_in[17];
    const float* lnf_b   = (const float*)d_in[18];
    const float* Wlm     = (const float*)d_in[19];
    const float* blm     = (const float*)d_in[20];
    float* out = (float*)d_out;

    float* x   = nullptr; cudaGetSymbolAddress((void**)&x,   g_x);
    float* h   = nullptr; cudaGetSymbolAddress((void**)&h,   g_h);
    float* qkv = nullptr; cudaGetSymbolAddress((void**)&qkv, g_qkv);
    float* att = nullptr; cudaGetSymbolAddress((void**)&att, g_att);
    float* a   = nullptr; cudaGetSymbolAddress((void**)&a,   g_a);
    float* ff  = nullptr; cudaGetSymbolAddress((void**)&ff,  g_ff);
    float* rowloss = nullptr; cudaGetSymbolAddress((void**)&rowloss, g_rowloss);
    uint32_t* wqkv16  = nullptr; cudaGetSymbolAddress((void**)&wqkv16,  g_wqkv16);
    uint32_t* wproj16 = nullptr; cudaGetSymbolAddress((void**)&wproj16, g_wproj16);
    uint32_t* w116    = nullptr; cudaGetSymbolAddress((void**)&w116,    g_w116);
    uint32_t* w216    = nullptr; cudaGetSymbolAddress((void**)&w216,    g_w216);
    uint32_t* wlm16   = nullptr; cudaGetSymbolAddress((void**)&wlm16,   g_wlm16);

    const float rs = rsqrtf((float)HS);
    const float* qp = qkv;
    const float* kp = qkv + (size_t)BT * CC;
    const float* vp = qkv + (size_t)2 * BT * CC;

    // ---- pack weights (every call; graph-capturable, deterministic) ----
    {
        size_t n;
        n = (size_t)LL * (CC / 2) * (3 * CC);
        pack_qkv_kernel<<<(unsigned)((n + 255) / 256), 256>>>(Wq, Wk, Wv, wqkv16);
        n = (size_t)LL * (CC / 2) * CC;
        pack_w_kernel<<<(unsigned)((n + 255) / 256), 256>>>(Wproj, wproj16, LL * CC / 2, CC, CC);
        n = (size_t)LL * (CC / 2) * FFD;
        pack_w_kernel<<<(unsigned)((n + 255) / 256), 256>>>(W1, w116, LL * CC / 2, FFD, FFD);
        n = (size_t)LL * (FFD / 2) * CC;
        pack_w_kernel<<<(unsigned)((n + 255) / 256), 256>>>(W2, w216, LL * FFD / 2, CC, CC);
        n = (size_t)(CC / 2) * VVP;
        pack_w_kernel<<<(unsigned)((n + 255) / 256), 256>>>(Wlm, wlm16, CC / 2, VV, VVP);
    }

    embed_kernel<<<(BT * CC + 255) / 256, 256>>>(idx, tok_emb, pos_emb, x);

    for (int l = 0; l < LL; l++) {
        const uint32_t* wqkv = wqkv16 + (size_t)l * (CC / 2) * (3 * CC);
        const uint32_t* wp   = wproj16 + (size_t)l * (CC / 2) * CC;
        const uint32_t* w1   = w116 + (size_t)l * (CC / 2) * FFD;
        const uint32_t* w2   = w216 + (size_t)l * (FFD / 2) * CC;
        const float* bp  = bproj + (size_t)l * CC;
        const float* bb1 = b1 + (size_t)l * FFD;
        const float* bb2 = b2 + (size_t)l * CC;

        ln_kernel<<<BT, 256>>>(x, ln1_g + (size_t)l * CC, ln1_b + (size_t)l * CC, h);

        // fused QKV: [BT, 3C] scattered to q|k|v [B,H,T,HS]
        gemm_tc<true,false,false,false,false,true,false><<<ggrid(BT, 3 * CC, 1), 256>>>(
            h, wqkv, nullptr, qkv, BT, 3 * CC, 3 * CC, CC, 1.f, 0, 0, 0);

        // scores = Q @ K^T * rs  (batched over B*H)
        gemm_tc<false,true,false,false,false,false,false><<<ggrid(TT, TT, BB * HH), 256>>>(
            qp, kp, nullptr, att, TT, TT, TT, HS, rs,
            (size_t)TT * HS, (size_t)TT * HS, (size_t)TT * TT);

        softmax_kernel<<<BB * HH * TT / 8, 256>>>(att);

        // A = softmax @ V  (batched)
        gemm_tc<false,false,false,false,false,false,false><<<ggrid(TT, HS, BB * HH), 256>>>(
            att, vp, nullptr, a, TT, HS, HS, TT, 1.f,
            (size_t)TT * TT, (size_t)TT * HS, (size_t)TT * HS);

        // x += attn_out @ Wproj + bproj  (A gathered from [B,H,T,HS])
        gemm_tc<true,false,true,false,true,false,true><<<ggrid(BT, CC, 1), 256>>>(
            a, wp, bp, x, BT, CC, CC, CC, 1.f, 0, 0, 0);

        ln_kernel<<<BT, 256>>>(x, ln2_g + (size_t)l * CC, ln2_b + (size_t)l * CC, h);

        // ff = relu(h @ W1 + b1)
        gemm_tc<true,false,true,true,false,false,false><<<ggrid(BT, FFD, 1), 256>>>(
            h, w1, bb1, ff, BT, FFD, FFD, CC, 1.f, 0, 0, 0);

        // x += ff @ W2 + b2
        gemm_tc<true,false,true,false,true,false,false><<<ggrid(BT, CC, 1), 256>>>(
            ff, w2, bb2, x, BT, CC, CC, FFD, 1.f, 0, 0, 0);
    }

    ln_kernel<<<BT, 256>>>(x, lnf_g, lnf_b, h);

    // logits = h @ Wlm + blm   (B padded to VVP; output bounded by VV)
    gemm_tc<true,false,true,false,false,false,false><<<ggrid(BT, VVP, 1), 256>>>(
        h, wlm16, blm, out, BT, VV, VVP, CC, 1.f, 0, 0, 0);

    rowloss_kernel<<<BT, 256>>>(out, targets, rowloss);
    if ((long long)out_size > (long long)BT * VV) {
        lossreduce_kernel<<<1, 256>>>(rowloss, out + (size_t)BT * VV);
    }
}

// round 10
// speedup vs baseline: 2.1615x; 1.1298x over previous
#include <cuda_runtime.h>
#include <cuda_fp16.h>
#include <math.h>
#include <stdint.h>

// ---------------- problem constants ----------------
constexpr int BB = 32, TT = 256, VV = 30522, CC = 768, HH = 8, LL = 10;
constexpr int HS = CC / HH;     // 96
constexpr int FFD = 4 * CC;     // 3072
constexpr int BT = BB * TT;     // 8192
constexpr int VVP = 30592;      // VV padded to multiple of 128
constexpr float LN_EPS = 1e-5f;

// ---------------- scratch ----------------
__device__ float g_x[BT * CC];                       // residual (f32)
__device__ uint32_t g_h16[BT * CC / 2];              // LN out, half2 pairs along C
__device__ uint32_t g_q16[BT * CC / 2];              // [B,H,T,HS/2]
__device__ uint32_t g_k16[BT * CC / 2];              // [B,H,T,HS/2]
__device__ float g_v[BT * CC];                       // [B,H,T,HS] f32
__device__ float g_att[(size_t)BB * HH * TT * TT];   // scores f32
__device__ uint32_t g_att16[(size_t)BB * HH * TT * TT / 2];  // softmax out, packed
__device__ uint32_t g_a16[BT * CC / 2];              // attn out [B,H,T,HS/2]
__device__ uint32_t g_ff16[(size_t)BT * FFD / 2];    // relu out packed
__device__ float g_rowloss[BT];
// pre-packed fp16 weights: [K/2][N] uint32 = half2(W[2k2][n], W[2k2+1][n])
__device__ uint32_t g_wqkv16[(size_t)LL * (CC / 2) * (3 * CC)];
__device__ uint32_t g_wproj16[(size_t)LL * (CC / 2) * CC];
__device__ uint32_t g_w116[(size_t)LL * (CC / 2) * FFD];
__device__ uint32_t g_w216[(size_t)LL * (FFD / 2) * CC];
__device__ uint32_t g_wlm16[(size_t)(CC / 2) * VVP];

__device__ __forceinline__ uint32_t f2h2(float lo, float hi) {
    uint32_t r;
    asm("{ .reg .f16 a, b; cvt.rn.f16.f32 a, %1; cvt.rn.f16.f32 b, %2; mov.b32 %0, {a, b}; }"
        : "=r"(r) : "f"(lo), "f"(hi));
    return r;
}

__device__ __forceinline__ void mma_fp16(float d[4], const uint32_t a[4], const uint32_t b[2]) {
    asm volatile(
        "mma.sync.aligned.m16n8k16.row.col.f32.f16.f16.f32 "
        "{%0,%1,%2,%3}, {%4,%5,%6,%7}, {%8,%9}, {%0,%1,%2,%3};\n"
        : "+f"(d[0]), "+f"(d[1]), "+f"(d[2]), "+f"(d[3])
        : "r"(a[0]), "r"(a[1]), "r"(a[2]), "r"(a[3]), "r"(b[0]), "r"(b[1]));
}

// ---------------- weight packing ----------------
__global__ void pack_w_kernel(const float* __restrict__ W, uint32_t* __restrict__ out,
                              int K2tot, int N, int Nb) {
    size_t i = (size_t)blockIdx.x * blockDim.x + threadIdx.x;
    if (i >= (size_t)K2tot * Nb) return;
    int k2 = (int)(i / Nb), n = (int)(i % Nb);
    float lo = 0.f, hi = 0.f;
    if (n < N) {
        lo = W[(size_t)(2 * k2) * N + n];
        hi = W[(size_t)(2 * k2 + 1) * N + n];
    }
    out[i] = f2h2(lo, hi);
}

__global__ void pack_qkv_kernel(const float* __restrict__ Wq, const float* __restrict__ Wk,
                                const float* __restrict__ Wv, uint32_t* __restrict__ out) {
    size_t i = (size_t)blockIdx.x * blockDim.x + threadIdx.x;
    const size_t total = (size_t)LL * (CC / 2) * (3 * CC);
    if (i >= total) return;
    int n = (int)(i % (3 * CC));
    size_t rest = i / (3 * CC);
    int k2 = (int)(rest % (CC / 2));
    int l = (int)(rest / (CC / 2));
    int which = n / CC, nn = n % CC;
    const float* W = (which == 0) ? Wq : (which == 1) ? Wk : Wv;
    const float* base = W + (size_t)l * CC * CC;
    out[i] = f2h2(base[(size_t)(2 * k2) * CC + nn], base[(size_t)(2 * k2 + 1) * CC + nn]);
}

// ---------------- embedding ----------------
__global__ void embed_kernel(const int* __restrict__ idx,
                             const float* __restrict__ tok,
                             const float* __restrict__ pos,
                             float* __restrict__ x) {
    int i = blockIdx.x * blockDim.x + threadIdx.x;
    if (i >= BT * CC) return;
    int bt = i / CC, c = i % CC;
    int t = bt % TT;
    x[i] = tok[(size_t)idx[bt] * CC + c] + pos[(size_t)t * CC + c];
}

// ---------------- layernorm -> packed fp16 ----------------
__global__ void ln_kernel(const float* __restrict__ x,
                          const float* __restrict__ g,
                          const float* __restrict__ b,
                          uint32_t* __restrict__ out16) {
    int row = blockIdx.x;
    const float* xr = x + (size_t)row * CC;
    uint32_t* orow = out16 + (size_t)row * (CC / 2);
    __shared__ float red[256];
    __shared__ float s_mu, s_inv;
    int tid = threadIdx.x;

    float s = 0.f;
    for (int c = tid; c < CC; c += 256) s += xr[c];
    red[tid] = s; __syncthreads();
    for (int st = 128; st > 0; st >>= 1) { if (tid < st) red[tid] += red[tid + st]; __syncthreads(); }
    if (tid == 0) s_mu = red[0] / CC;
    __syncthreads();
    float mu = s_mu;

    float v = 0.f;
    for (int c = tid; c < CC; c += 256) { float d = xr[c] - mu; v += d * d; }
    red[tid] = v; __syncthreads();
    for (int st = 128; st > 0; st >>= 1) { if (tid < st) red[tid] += red[tid + st]; __syncthreads(); }
    if (tid == 0) s_inv = rsqrtf(red[0] / CC + LN_EPS);
    __syncthreads();
    float inv = s_inv;

    for (int c2 = tid; c2 < CC / 2; c2 += 256) {
        int c = 2 * c2;
        float v0 = (xr[c] - mu) * inv * g[c] + b[c];
        float v1 = (xr[c + 1] - mu) * inv * g[c + 1] + b[c + 1];
        orow[c2] = f2h2(v0, v1);
    }
}

// ---------------- fp16 tensor-core GEMM: 128x128x32, m16n8k16 ----------------
// A is ALWAYS packed half2-pairs along K (uint32 words).
// AM: 0 = flat [row][K/2] (+ batch stride sA words)
//     1 = gather from [B,H,T,HS/2] (row -> (b,t), k -> (h,d))
// BMo: 0 = packed weights [K/2][Nb] words
//      1 = packed transposed [n][K/2] words (+ batch stride sB words)
//      2 = f32 [K][N] (+ batch stride sB elems)
// OM: 0 = f32 [row][N] (+ sC elems), guarded for odd N
//     1 = QKV scatter: q16/k16 packed via Cw, v f32 via Caux
//     2 = packed pairs along N: [row][N/2] words (+ sC words)
template<int AM, int BMo, bool BIAS, bool RELU, bool ACC, int OM>
__global__ __launch_bounds__(256, 2)
void gemm_tc(const uint32_t* __restrict__ A, const void* __restrict__ Bmv,
             const float* __restrict__ bias, void* __restrict__ Cmv,
             float* __restrict__ Caux,
             int M, int N, int Nb, int K, float alpha,
             size_t sA, size_t sB, size_t sC) {
    constexpr int BM = 128, BN = 128, BK = 32;
    constexpr int SA = 20;
    constexpr int SBW = 136;
    __shared__ __align__(16) uint32_t As2[2][BM][SA];
    __shared__ __align__(16) uint32_t Bs2[2][BK / 2][SBW];

    const uint32_t* Ab = A + (size_t)blockIdx.z * sA;
    const uint32_t* Bw = (const uint32_t*)Bmv + ((BMo == 1) ? (size_t)blockIdx.z * sB : 0);
    const float* Bf = (const float*)Bmv + ((BMo == 2) ? (size_t)blockIdx.z * sB : 0);

    int bm = blockIdx.y * BM;
    int bn = blockIdx.x * BN;
    int tid = threadIdx.x;
    int wid = tid >> 5, lane = tid & 31;
    int wm = (wid & 1) * 64;
    int wn = (wid >> 1) * 32;
    int gq = lane >> 2;
    int cq = lane & 3;

    float acc[4][4][4];
    #pragma unroll
    for (int i = 0; i < 4; i++)
        #pragma unroll
        for (int j = 0; j < 4; j++)
            #pragma unroll
            for (int t = 0; t < 4; t++) acc[i][j][t] = 0.f;

    uint4 rAu[2];
    uint4 rBu[2];
    uint32_t rB[8];

    auto loadA = [&](int k0) {
        #pragma unroll
        for (int r = 0; r < 2; r++) {
            int id = tid + r * 256;          // 512 uint4 slots (128 rows x 4)
            int m = id >> 2, k2q = (id & 3) * 4;
            int row = bm + m;
            const uint32_t* src;
            if (AM == 0) {
                src = Ab + (size_t)row * (K / 2) + (k0 / 2 + k2q);
            } else {
                int k = k0 + 2 * k2q;
                int b = row / TT, t = row % TT, hh = k / HS, d = k % HS;
                src = Ab + (((size_t)b * HH + hh) * TT + t) * (HS / 2) + d / 2;
            }
            rAu[r] = *reinterpret_cast<const uint4*>(src);
        }
    };
    auto storeA = [&](int buf) {
        #pragma unroll
        for (int r = 0; r < 2; r++) {
            int id = tid + r * 256;
            int m = id >> 2, k2q = (id & 3) * 4;
            *reinterpret_cast<uint4*>(&As2[buf][m][k2q]) = rAu[r];
        }
    };
    auto loadB = [&](int k0) {
        if (BMo == 0) {
            #pragma unroll
            for (int r = 0; r < 2; r++) {
                int id = tid + r * 256;
                int k2 = id >> 5;                // 0..15
                int n4 = (id & 31) * 4;
                rBu[r] = *reinterpret_cast<const uint4*>(
                    &Bw[(size_t)(k0 / 2 + k2) * Nb + bn + n4]);
            }
        } else if (BMo == 1) {
            #pragma unroll
            for (int r = 0; r < 2; r++) {
                int id = tid + r * 256;          // 512 uint4 slots (128 n x 4)
                int n = id >> 2, k2q = (id & 3) * 4;
                rBu[r] = *reinterpret_cast<const uint4*>(
                    &Bw[(size_t)(bn + n) * (K / 2) + (k0 / 2 + k2q)]);
            }
        } else {
            #pragma unroll
            for (int r = 0; r < 2; r++) {
                int id = tid + r * 256;
                int k2 = id >> 5;
                int n4 = (id & 31) * 4;
                int gk = k0 + 2 * k2;
                int gn = bn + n4;
                float4 v0, v1;
                if (((N & 3) == 0) && (gn + 3 < N)) {
                    v0 = *reinterpret_cast<const float4*>(&Bf[(size_t)gk * N + gn]);
                    v1 = *reinterpret_cast<const float4*>(&Bf[(size_t)(gk + 1) * N + gn]);
                } else {
                    float t0[4], t1[4];
                    #pragma unroll
                    for (int j = 0; j < 4; j++) {
                        int g = gn + j;
                        t0[j] = (g < N) ? Bf[(size_t)gk * N + g] : 0.f;
                        t1[j] = (g < N) ? Bf[(size_t)(gk + 1) * N + g] : 0.f;
                    }
                    v0 = make_float4(t0[0], t0[1], t0[2], t0[3]);
                    v1 = make_float4(t1[0], t1[1], t1[2], t1[3]);
                }
                rB[r * 4 + 0] = f2h2(v0.x, v1.x);
                rB[r * 4 + 1] = f2h2(v0.y, v1.y);
                rB[r * 4 + 2] = f2h2(v0.z, v1.z);
                rB[r * 4 + 3] = f2h2(v0.w, v1.w);
            }
        }
    };
    auto storeB = [&](int buf) {
        if (BMo == 0) {
            #pragma unroll
            for (int r = 0; r < 2; r++) {
                int id = tid + r * 256;
                int k2 = id >> 5;
                int n4 = (id & 31) * 4;
                *reinterpret_cast<uint4*>(&Bs2[buf][k2][n4]) = rBu[r];
            }
        } else if (BMo == 1) {
            #pragma unroll
            for (int r = 0; r < 2; r++) {
                int id = tid + r * 256;
                int n = id >> 2, k2q = (id & 3) * 4;
                Bs2[buf][k2q + 0][n] = rBu[r].x;
                Bs2[buf][k2q + 1][n] = rBu[r].y;
                Bs2[buf][k2q + 2][n] = rBu[r].z;
                Bs2[buf][k2q + 3][n] = rBu[r].w;
            }
        } else {
            #pragma unroll
            for (int r = 0; r < 2; r++) {
                int id = tid + r * 256;
                int k2 = id >> 5;
                int n4 = (id & 31) * 4;
                uint4 v = make_uint4(rB[r * 4 + 0], rB[r * 4 + 1], rB[r * 4 + 2], rB[r * 4 + 3]);
                *reinterpret_cast<uint4*>(&Bs2[buf][k2][n4]) = v;
            }
        }
    };

    // prologue
    loadA(0); loadB(0);
    storeA(0); storeB(0);
    __syncthreads();

    int cur = 0;
    for (int k0 = 0; k0 < K; k0 += BK) {
        bool has_next = (k0 + BK) < K;
        if (has_next) { loadA(k0 + BK); loadB(k0 + BK); }

        #pragma unroll
        for (int kk2 = 0; kk2 < BK / 2; kk2 += 8) {
            uint32_t af[4][4];
            uint32_t bf[4][2];
            #pragma unroll
            for (int i = 0; i < 4; i++) {
                int mr = wm + i * 16;
                af[i][0] = As2[cur][mr + gq][kk2 + cq];
                af[i][1] = As2[cur][mr + gq + 8][kk2 + cq];
                af[i][2] = As2[cur][mr + gq][kk2 + cq + 4];
                af[i][3] = As2[cur][mr + gq + 8][kk2 + cq + 4];
            }
            #pragma unroll
            for (int j = 0; j < 4; j++) {
                int nc = wn + j * 8 + gq;
                bf[j][0] = Bs2[cur][kk2 + cq][nc];
                bf[j][1] = Bs2[cur][kk2 + cq + 4][nc];
            }
            #pragma unroll
            for (int i = 0; i < 4; i++)
                #pragma unroll
                for (int j = 0; j < 4; j++)
                    mma_fp16(acc[i][j], af[i], bf[j]);
        }

        if (has_next) { storeA(cur ^ 1); storeB(cur ^ 1); }
        __syncthreads();
        cur ^= 1;
    }

    // epilogue
    float* Cf = (float*)Cmv + ((OM == 0) ? (size_t)blockIdx.z * sC : 0);
    uint32_t* Cw = (uint32_t*)Cmv + ((OM == 2) ? (size_t)blockIdx.z * sC : 0);

    #pragma unroll
    for (int i = 0; i < 4; i++) {
        int r0 = bm + wm + i * 16 + gq;
        #pragma unroll
        for (int j = 0; j < 4; j++) {
            int c0 = bn + wn + j * 8 + cq * 2;
            if (c0 >= N) continue;
            #pragma unroll
            for (int half = 0; half < 2; half++) {
                int row = r0 + half * 8;
                float v0 = acc[i][j][half * 2 + 0] * alpha;
                float v1 = acc[i][j][half * 2 + 1] * alpha;
                if (BIAS) { v0 += bias[c0]; v1 += (c0 + 1 < N) ? bias[c0 + 1] : 0.f; }
                if (RELU) { v0 = fmaxf(v0, 0.f); v1 = fmaxf(v1, 0.f); }

                if (OM == 1) {
                    int which = c0 / CC, cc = c0 % CC;
                    int b = row / TT, t = row % TT, hh = cc / HS, d = cc % HS;
                    size_t base = ((size_t)b * HH + hh) * TT + t;
                    if (which == 0) {
                        Cw[base * (HS / 2) + d / 2] = f2h2(v0, v1);
                    } else if (which == 1) {
                        Cw[(size_t)BT * (CC / 2) + base * (HS / 2) + d / 2] = f2h2(v0, v1);
                    } else {
                        *reinterpret_cast<float2*>(&Caux[base * HS + d]) = make_float2(v0, v1);
                    }
                } else if (OM == 2) {
                    Cw[(size_t)row * (N / 2) + c0 / 2] = f2h2(v0, v1);
                } else {
                    size_t oidx = (size_t)row * N + c0;
                    if (c0 + 1 < N) {
                        if (ACC) {
                            float2 old = *reinterpret_cast<float2*>(&Cf[oidx]);
                            v0 += old.x; v1 += old.y;
                        }
                        *reinterpret_cast<float2*>(&Cf[oidx]) = make_float2(v0, v1);
                    } else {
                        if (ACC) v0 += Cf[oidx];
                        Cf[oidx] = v0;
                    }
                }
            }
        }
    }
}

// ---------------- causal softmax: f32 in, packed fp16 out ----------------
__global__ void softmax_kernel(const float* __restrict__ att, uint32_t* __restrict__ att16) {
    int warp = threadIdx.x >> 5, lane = threadIdx.x & 31;
    size_t row = (size_t)blockIdx.x * 8 + warp;
    int qi = (int)(row % TT);
    const float* w = att + row * (size_t)TT;
    uint32_t* w16 = att16 + row * (size_t)(TT / 2);

    int i0 = lane * 4, i1 = 128 + lane * 4;
    float4 a0 = *reinterpret_cast<const float4*>(&w[i0]);
    float4 a1 = *reinterpret_cast<const float4*>(&w[i1]);
    float v[8] = {a0.x, a0.y, a0.z, a0.w, a1.x, a1.y, a1.z, a1.w};
    int base[2] = {i0, i1};

    float mx = -1e30f;
    #pragma unroll
    for (int h = 0; h < 2; h++)
        #pragma unroll
        for (int j = 0; j < 4; j++)
            if (base[h] + j <= qi) mx = fmaxf(mx, v[h * 4 + j]);
    #pragma unroll
    for (int s = 16; s > 0; s >>= 1) mx = fmaxf(mx, __shfl_xor_sync(0xffffffffu, mx, s));

    float e[8];
    float sum = 0.f;
    #pragma unroll
    for (int h = 0; h < 2; h++)
        #pragma unroll
        for (int j = 0; j < 4; j++) {
            int idx = h * 4 + j;
            e[idx] = (base[h] + j <= qi) ? expf(v[idx] - mx) : 0.f;
            sum += e[idx];
        }
    #pragma unroll
    for (int s = 16; s > 0; s >>= 1) sum += __shfl_xor_sync(0xffffffffu, sum, s);
    float inv = 1.f / sum;

    uint2 o0 = make_uint2(f2h2(e[0] * inv, e[1] * inv), f2h2(e[2] * inv, e[3] * inv));
    uint2 o1 = make_uint2(f2h2(e[4] * inv, e[5] * inv), f2h2(e[6] * inv, e[7] * inv));
    *reinterpret_cast<uint2*>(&w16[lane * 2]) = o0;
    *reinterpret_cast<uint2*>(&w16[64 + lane * 2]) = o1;
}

// ---------------- loss ----------------
__global__ void rowloss_kernel(const float* __restrict__ logits,
                               const int* __restrict__ targets,
                               float* __restrict__ rowloss) {
    int r = blockIdx.x;
    const float* lr = logits + (size_t)r * VV;
    int tid = threadIdx.x;
    __shared__ float red[256];
    __shared__ float s_mx;

    float mx = -1e30f;
    for (int c = tid; c < VV; c += 256) mx = fmaxf(mx, lr[c]);
    red[tid] = mx; __syncthreads();
    for (int st = 128; st > 0; st >>= 1) { if (tid < st) red[tid] = fmaxf(red[tid], red[tid + st]); __syncthreads(); }
    if (tid == 0) s_mx = red[0];
    __syncthreads();
    mx = s_mx;

    float s = 0.f;
    for (int c = tid; c < VV; c += 256) s += expf(lr[c] - mx);
    red[tid] = s; __syncthreads();
    for (int st = 128; st > 0; st >>= 1) { if (tid < st) red[tid] += red[tid + st]; __syncthreads(); }
    if (tid == 0) {
        int t = targets[r];
        rowloss[r] = -(lr[t] - mx - logf(red[0]));
    }
}

__global__ void lossreduce_kernel(const float* __restrict__ rowloss, float* __restrict__ out) {
    __shared__ float red[256];
    int tid = threadIdx.x;
    float s = 0.f;
    for (int r = tid; r < BT; r += 256) s += rowloss[r];
    red[tid] = s; __syncthreads();
    for (int st = 128; st > 0; st >>= 1) { if (tid < st) red[tid] += red[tid + st]; __syncthreads(); }
    if (tid == 0) out[0] = red[0] / BT;
}

// ---------------- host ----------------
static inline dim3 ggrid(int M, int N, int batch) {
    return dim3((N + 127) / 128, (M + 127) / 128, batch);
}

extern "C" void kernel_launch(void* const* d_in, const int* in_sizes, int n_in,
                              void* d_out, int out_size) {
    const int*   idx     = (const int*)  d_in[0];
    const int*   targets = (const int*)  d_in[1];
    const float* tok_emb = (const float*)d_in[2];
    const float* pos_emb = (const float*)d_in[3];
    const float* Wq      = (const float*)d_in[4];
    const float* Wk      = (const float*)d_in[5];
    const float* Wv      = (const float*)d_in[6];
    const float* Wproj   = (const float*)d_in[7];
    const float* bproj   = (const float*)d_in[8];
    const float* W1      = (const float*)d_in[9];
    const float* b1      = (const float*)d_in[10];
    const float* W2      = (const float*)d_in[11];
    const float* b2      = (const float*)d_in[12];
    const float* ln1_g   = (const float*)d_in[13];
    const float* ln1_b   = (const float*)d_in[14];
    const float* ln2_g   = (const float*)d_in[15];
    const float* ln2_b   = (const float*)d_in[16];
    const float* lnf_g   = (const float*)d_in[17];
    const float* lnf_b   = (const float*)d_in[18];
    const float* Wlm     = (const float*)d_in[19];
    const float* blm     = (const float*)d_in[20];
    float* out = (float*)d_out;

    float* x    = nullptr; cudaGetSymbolAddress((void**)&x,    g_x);
    uint32_t* h16 = nullptr; cudaGetSymbolAddress((void**)&h16, g_h16);
    uint32_t* q16 = nullptr; cudaGetSymbolAddress((void**)&q16, g_q16);
    uint32_t* k16 = nullptr; cudaGetSymbolAddress((void**)&k16, g_k16);
    float* v    = nullptr; cudaGetSymbolAddress((void**)&v,    g_v);
    float* att  = nullptr; cudaGetSymbolAddress((void**)&att,  g_att);
    uint32_t* att16 = nullptr; cudaGetSymbolAddress((void**)&att16, g_att16);
    uint32_t* a16 = nullptr; cudaGetSymbolAddress((void**)&a16, g_a16);
    uint32_t* ff16 = nullptr; cudaGetSymbolAddress((void**)&ff16, g_ff16);
    float* rowloss = nullptr; cudaGetSymbolAddress((void**)&rowloss, g_rowloss);
    uint32_t* wqkv16  = nullptr; cudaGetSymbolAddress((void**)&wqkv16,  g_wqkv16);
    uint32_t* wproj16 = nullptr; cudaGetSymbolAddress((void**)&wproj16, g_wproj16);
    uint32_t* w116    = nullptr; cudaGetSymbolAddress((void**)&w116,    g_w116);
    uint32_t* w216    = nullptr; cudaGetSymbolAddress((void**)&w216,    g_w216);
    uint32_t* wlm16   = nullptr; cudaGetSymbolAddress((void**)&wlm16,   g_wlm16);

    const float rs = rsqrtf((float)HS);

    // ---- pack weights ----
    {
        size_t n;
        n = (size_t)LL * (CC / 2) * (3 * CC);
        pack_qkv_kernel<<<(unsigned)((n + 255) / 256), 256>>>(Wq, Wk, Wv, wqkv16);
        n = (size_t)LL * (CC / 2) * CC;
        pack_w_kernel<<<(unsigned)((n + 255) / 256), 256>>>(Wproj, wproj16, LL * CC / 2, CC, CC);
        n = (size_t)LL * (CC / 2) * FFD;
        pack_w_kernel<<<(unsigned)((n + 255) / 256), 256>>>(W1, w116, LL * CC / 2, FFD, FFD);
        n = (size_t)LL * (FFD / 2) * CC;
        pack_w_kernel<<<(unsigned)((n + 255) / 256), 256>>>(W2, w216, LL * FFD / 2, CC, CC);
        n = (size_t)(CC / 2) * VVP;
        pack_w_kernel<<<(unsigned)((n + 255) / 256), 256>>>(Wlm, wlm16, CC / 2, VV, VVP);
    }

    embed_kernel<<<(BT * CC + 255) / 256, 256>>>(idx, tok_emb, pos_emb, x);

    for (int l = 0; l < LL; l++) {
        const uint32_t* wqkv = wqkv16 + (size_t)l * (CC / 2) * (3 * CC);
        const uint32_t* wp   = wproj16 + (size_t)l * (CC / 2) * CC;
        const uint32_t* w1   = w116 + (size_t)l * (CC / 2) * FFD;
        const uint32_t* w2   = w216 + (size_t)l * (FFD / 2) * CC;
        const float* bp  = bproj + (size_t)l * CC;
        const float* bb1 = b1 + (size_t)l * FFD;
        const float* bb2 = b2 + (size_t)l * CC;

        ln_kernel<<<BT, 256>>>(x, ln1_g + (size_t)l * CC, ln1_b + (size_t)l * CC, h16);

        // fused QKV: q16|k16 packed, v f32
        gemm_tc<0, 0, false, false, false, 1><<<ggrid(BT, 3 * CC, 1), 256>>>(
            h16, wqkv, nullptr, q16, v, BT, 3 * CC, 3 * CC, CC, 1.f, 0, 0, 0);

        // scores = Q @ K^T * rs  (batched over B*H): A=q16 flat, B=k16 transposed-packed
        gemm_tc<0, 1, false, false, false, 0><<<ggrid(TT, TT, BB * HH), 256>>>(
            q16, k16, nullptr, att, nullptr, TT, TT, TT, HS, rs,
            (size_t)TT * (HS / 2), (size_t)TT * (HS / 2), (size_t)TT * TT);

        softmax_kernel<<<BB * HH * TT / 8, 256>>>(att, att16);

        // A = softmax @ V  (batched): A=att16 flat, B=v f32; out packed a16
        gemm_tc<0, 2, false, false, false, 2><<<ggrid(TT, HS, BB * HH), 256>>>(
            att16, v, nullptr, a16, nullptr, TT, HS, HS, TT, 1.f,
            (size_t)TT * (TT / 2), (size_t)TT * HS, (size_t)TT * (HS / 2));

        // x += attn_out @ Wproj + bproj  (A gathered packed from [B,H,T,HS/2])
        gemm_tc<1, 0, true, false, true, 0><<<ggrid(BT, CC, 1), 256>>>(
            a16, wp, bp, x, nullptr, BT, CC, CC, CC, 1.f, 0, 0, 0);

        ln_kernel<<<BT, 256>>>(x, ln2_g + (size_t)l * CC, ln2_b + (size_t)l * CC, h16);

        // ff16 = relu(h @ W1 + b1), packed
        gemm_tc<0, 0, true, true, false, 2><<<ggrid(BT, FFD, 1), 256>>>(
            h16, w1, bb1, ff16, nullptr, BT, FFD, FFD, CC, 1.f, 0, 0, 0);

        // x += ff @ W2 + b2
        gemm_tc<0, 0, true, false, true, 0><<<ggrid(BT, CC, 1), 256>>>(
            ff16, w2, bb2, x, nullptr, BT, CC, CC, FFD, 1.f, 0, 0, 0);
    }

    ln_kernel<<<BT, 256>>>(x, lnf_g, lnf_b, h16);

    // logits = h @ Wlm + blm
    gemm_tc<0, 0, true, false, false, 0><<<ggrid(BT, VVP, 1), 256>>>(
        h16, wlm16, blm, out, nullptr, BT, VV, VVP, CC, 1.f, 0, 0, 0);

    rowloss_kernel<<<BT, 256>>>(out, targets, rowloss);
    if ((long long)out_size > (long long)BT * VV) {
        lossreduce_kernel<<<1, 256>>>(rowloss, out + (size_t)BT * VV);
    }
}

// round 11
// speedup vs baseline: 2.3830x; 1.1025x over previous
#include <cuda_runtime.h>
#include <cuda_fp16.h>
#include <math.h>
#include <stdint.h>

// ---------------- problem constants ----------------
constexpr int BB = 32, TT = 256, VV = 30522, CC = 768, HH = 8, LL = 10;
constexpr int HS = CC / HH;     // 96
constexpr int FFD = 4 * CC;     // 3072
constexpr int BT = BB * TT;     // 8192
constexpr int VVP = 30592;      // VV padded to multiple of 128
constexpr float LN_EPS = 1e-5f;

// ---------------- scratch ----------------
__device__ float g_x[BT * CC];                       // residual (f32)
__device__ uint32_t g_h16[BT * CC / 2];              // LN out, half2 pairs along C
__device__ uint32_t g_qk16[BT * CC];                 // q | k packed, each BT*CC/2 words
__device__ uint32_t g_v16t[BT * CC / 2 + 4096];      // V [B,H,HS,T] halves (padded for OOB staging)
__device__ float g_att[(size_t)BB * HH * TT * TT];   // scores f32
__device__ uint32_t g_att16[(size_t)BB * HH * TT * TT / 2];
__device__ uint32_t g_a16[BT * CC / 2];              // attn out [B,H,T,HS/2]
__device__ uint32_t g_ff16[(size_t)BT * FFD / 2];
__device__ float g_rowloss[BT];
// pre-packed fp16 weights: [K/2][N] uint32 = half2(W[2k2][n], W[2k2+1][n])
__device__ uint32_t g_wqkv16[(size_t)LL * (CC / 2) * (3 * CC)];
__device__ uint32_t g_wproj16[(size_t)LL * (CC / 2) * CC];
__device__ uint32_t g_w116[(size_t)LL * (CC / 2) * FFD];
__device__ uint32_t g_w216[(size_t)LL * (FFD / 2) * CC];
__device__ uint32_t g_wlm16[(size_t)(CC / 2) * VVP];

__device__ __forceinline__ uint32_t f2h2(float lo, float hi) {
    uint32_t r;
    asm("{ .reg .f16 a, b; cvt.rn.f16.f32 a, %1; cvt.rn.f16.f32 b, %2; mov.b32 %0, {a, b}; }"
        : "=r"(r) : "f"(lo), "f"(hi));
    return r;
}

__device__ __forceinline__ void mma_fp16(float d[4], const uint32_t a[4], const uint32_t b[2]) {
    asm volatile(
        "mma.sync.aligned.m16n8k16.row.col.f32.f16.f16.f32 "
        "{%0,%1,%2,%3}, {%4,%5,%6,%7}, {%8,%9}, {%0,%1,%2,%3};\n"
        : "+f"(d[0]), "+f"(d[1]), "+f"(d[2]), "+f"(d[3])
        : "r"(a[0]), "r"(a[1]), "r"(a[2]), "r"(a[3]), "r"(b[0]), "r"(b[1]));
}

__device__ __forceinline__ void cp16(uint32_t dst, const void* src) {
    asm volatile("cp.async.cg.shared.global [%0], [%1], 16;" :: "r"(dst), "l"(src) : "memory");
}

// ---------------- weight packing ----------------
__global__ void pack_w_kernel(const float* __restrict__ W, uint32_t* __restrict__ out,
                              int K2tot, int N, int Nb) {
    size_t i = (size_t)blockIdx.x * blockDim.x + threadIdx.x;
    if (i >= (size_t)K2tot * Nb) return;
    int k2 = (int)(i / Nb), n = (int)(i % Nb);
    float lo = 0.f, hi = 0.f;
    if (n < N) {
        lo = W[(size_t)(2 * k2) * N + n];
        hi = W[(size_t)(2 * k2 + 1) * N + n];
    }
    out[i] = f2h2(lo, hi);
}

__global__ void pack_qkv_kernel(const float* __restrict__ Wq, const float* __restrict__ Wk,
                                const float* __restrict__ Wv, uint32_t* __restrict__ out) {
    size_t i = (size_t)blockIdx.x * blockDim.x + threadIdx.x;
    const size_t total = (size_t)LL * (CC / 2) * (3 * CC);
    if (i >= total) return;
    int n = (int)(i % (3 * CC));
    size_t rest = i / (3 * CC);
    int k2 = (int)(rest % (CC / 2));
    int l = (int)(rest / (CC / 2));
    int which = n / CC, nn = n % CC;
    const float* W = (which == 0) ? Wq : (which == 1) ? Wk : Wv;
    const float* base = W + (size_t)l * CC * CC;
    out[i] = f2h2(base[(size_t)(2 * k2) * CC + nn], base[(size_t)(2 * k2 + 1) * CC + nn]);
}

// ---------------- embedding ----------------
__global__ void embed_kernel(const int* __restrict__ idx,
                             const float* __restrict__ tok,
                             const float* __restrict__ pos,
                             float* __restrict__ x) {
    int i = blockIdx.x * blockDim.x + threadIdx.x;
    if (i >= BT * CC) return;
    int bt = i / CC, c = i % CC;
    int t = bt % TT;
    x[i] = tok[(size_t)idx[bt] * CC + c] + pos[(size_t)t * CC + c];
}

// ---------------- layernorm -> packed fp16 ----------------
__global__ void ln_kernel(const float* __restrict__ x,
                          const float* __restrict__ g,
                          const float* __restrict__ b,
                          uint32_t* __restrict__ out16) {
    int row = blockIdx.x;
    const float* xr = x + (size_t)row * CC;
    uint32_t* orow = out16 + (size_t)row * (CC / 2);
    __shared__ float red[256];
    __shared__ float s_mu, s_inv;
    int tid = threadIdx.x;

    float s = 0.f;
    for (int c = tid; c < CC; c += 256) s += xr[c];
    red[tid] = s; __syncthreads();
    for (int st = 128; st > 0; st >>= 1) { if (tid < st) red[tid] += red[tid + st]; __syncthreads(); }
    if (tid == 0) s_mu = red[0] / CC;
    __syncthreads();
    float mu = s_mu;

    float v = 0.f;
    for (int c = tid; c < CC; c += 256) { float d = xr[c] - mu; v += d * d; }
    red[tid] = v; __syncthreads();
    for (int st = 128; st > 0; st >>= 1) { if (tid < st) red[tid] += red[tid + st]; __syncthreads(); }
    if (tid == 0) s_inv = rsqrtf(red[0] / CC + LN_EPS);
    __syncthreads();
    float inv = s_inv;

    for (int c2 = tid; c2 < CC / 2; c2 += 256) {
        int c = 2 * c2;
        float v0 = (xr[c] - mu) * inv * g[c] + b[c];
        float v1 = (xr[c + 1] - mu) * inv * g[c + 1] + b[c + 1];
        orow[c2] = f2h2(v0, v1);
    }
}

// ---------------- fp16 GEMM, cp.async 4-stage, 128x128x32 m16n8k16 ----------------
// A: packed half2-pairs along K.
//   AM 0 = flat [row][K/2] (+sA words batch stride); 1 = gather [B,H,T,HS/2]
// B: BMo 0 = packed weights [K/2][Nb]; 1 = packed transposed [n][K/2] (+sB words)
// Out: OM 0 = f32 [row][N] (+sC elems); 1 = QKV scatter (q/k packed -> Cw, v -> v16t Caux);
//      2 = packed pairs along N [row][N/2] (+sC words)
constexpr int GNS = 4;                    // pipeline stages
constexpr int GAW = 128 * 20;             // A stage words
constexpr int GBW = 128 * 20;             // B stage words (covers both layouts)
constexpr int GSTW = GAW + GBW;
constexpr int GDSM = GNS * GSTW * 4;      // dynamic smem bytes = 81920

template<int AM, int BMo, bool BIAS, bool RELU, bool ACC, int OM>
__global__ __launch_bounds__(256, 2)
void gemm_tc(const uint32_t* __restrict__ A, const uint32_t* __restrict__ Bw,
             const float* __restrict__ bias, void* __restrict__ Cmv,
             void* __restrict__ Caux,
             int M, int N, int Nb, int K, float alpha,
             size_t sA, size_t sB, size_t sC) {
    constexpr int BK = 32;
    extern __shared__ __align__(16) uint32_t smw[];
    uint32_t smb = (uint32_t)__cvta_generic_to_shared(smw);

    const uint32_t* Ab = A + (size_t)blockIdx.z * sA;
    const uint32_t* Bb = Bw + ((BMo == 1) ? (size_t)blockIdx.z * sB : 0);

    int bm = blockIdx.y * 128;
    int bn = blockIdx.x * 128;
    int tid = threadIdx.x;
    int wid = tid >> 5, lane = tid & 31;
    int wm = (wid & 1) * 64;
    int wn = (wid >> 1) * 32;
    int gq = lane >> 2;
    int cq = lane & 3;

    const int nIter = K / BK;

    float acc[4][4][4];
    #pragma unroll
    for (int i = 0; i < 4; i++)
        #pragma unroll
        for (int j = 0; j < 4; j++)
            #pragma unroll
            for (int t = 0; t < 4; t++) acc[i][j][t] = 0.f;

    auto issue_stage = [&](int it) {
        if (it < nIter) {
            int k0 = it * BK;
            int st = it & (GNS - 1);
            uint32_t abase = smb + (uint32_t)(st * GSTW) * 4;
            uint32_t bbase = abase + GAW * 4;
            #pragma unroll
            for (int r = 0; r < 2; r++) {
                int id = tid + r * 256;
                {   // A chunk: 16 bytes = 4 words
                    int m = id >> 2, k2q = (id & 3) * 4;
                    int row = bm + m;
                    const uint32_t* g;
                    if (AM == 0) {
                        g = Ab + (size_t)row * (K / 2) + (k0 / 2 + k2q);
                    } else {
                        int k = k0 + 2 * k2q;
                        int b = row / TT, t = row % TT, hh = k / HS, d = k % HS;
                        g = Ab + (((size_t)b * HH + hh) * TT + t) * (HS / 2) + d / 2;
                    }
                    cp16(abase + (uint32_t)(m * 20 + k2q) * 4, g);
                }
                if (BMo == 0) {
                    int k2 = id >> 5, n4 = (id & 31) * 4;
                    const uint32_t* g = Bb + (size_t)(k0 / 2 + k2) * Nb + bn + n4;
                    cp16(bbase + (uint32_t)(k2 * 136 + n4) * 4, g);
                } else {
                    int n = id >> 2, k2q = (id & 3) * 4;
                    const uint32_t* g = Bb + (size_t)(bn + n) * (K / 2) + (k0 / 2 + k2q);
                    cp16(bbase + (uint32_t)(n * 20 + k2q) * 4, g);
                }
            }
        }
        asm volatile("cp.async.commit_group;" ::: "memory");
    };

    #pragma unroll
    for (int s = 0; s < GNS - 1; s++) issue_stage(s);

    for (int it = 0; it < nIter; ++it) {
        asm volatile("cp.async.wait_group 2;" ::: "memory");
        __syncthreads();
        issue_stage(it + GNS - 1);

        const uint32_t* As_ = smw + (it & (GNS - 1)) * GSTW;
        const uint32_t* Bs_ = As_ + GAW;

        #pragma unroll
        for (int kk2 = 0; kk2 < BK / 2; kk2 += 8) {
            uint32_t af[4][4];
            uint32_t bf[4][2];
            #pragma unroll
            for (int i = 0; i < 4; i++) {
                int mr = wm + i * 16;
                af[i][0] = As_[(mr + gq) * 20 + kk2 + cq];
                af[i][1] = As_[(mr + gq + 8) * 20 + kk2 + cq];
                af[i][2] = As_[(mr + gq) * 20 + kk2 + cq + 4];
                af[i][3] = As_[(mr + gq + 8) * 20 + kk2 + cq + 4];
            }
            #pragma unroll
            for (int j = 0; j < 4; j++) {
                int nc = wn + j * 8 + gq;
                if (BMo == 0) {
                    bf[j][0] = Bs_[(kk2 + cq) * 136 + nc];
                    bf[j][1] = Bs_[(kk2 + cq + 4) * 136 + nc];
                } else {
                    bf[j][0] = Bs_[nc * 20 + kk2 + cq];
                    bf[j][1] = Bs_[nc * 20 + kk2 + cq + 4];
                }
            }
            #pragma unroll
            for (int i = 0; i < 4; i++)
                #pragma unroll
                for (int j = 0; j < 4; j++)
                    mma_fp16(acc[i][j], af[i], bf[j]);
        }
    }

    // epilogue
    float* Cf = (float*)Cmv + ((OM == 0) ? (size_t)blockIdx.z * sC : 0);
    uint32_t* Cw = (uint32_t*)Cmv + ((OM == 2) ? (size_t)blockIdx.z * sC : 0);

    #pragma unroll
    for (int i = 0; i < 4; i++) {
        int r0 = bm + wm + i * 16 + gq;
        #pragma unroll
        for (int j = 0; j < 4; j++) {
            int c0 = bn + wn + j * 8 + cq * 2;
            if (c0 >= N) continue;
            #pragma unroll
            for (int half = 0; half < 2; half++) {
                int row = r0 + half * 8;
                float v0 = acc[i][j][half * 2 + 0] * alpha;
                float v1 = acc[i][j][half * 2 + 1] * alpha;
                if (BIAS) { v0 += bias[c0]; v1 += (c0 + 1 < N) ? bias[c0 + 1] : 0.f; }
                if (RELU) { v0 = fmaxf(v0, 0.f); v1 = fmaxf(v1, 0.f); }

                if (OM == 1) {
                    int which = c0 / CC, cc = c0 % CC;
                    int b = row / TT, t = row % TT, hh = cc / HS, d = cc % HS;
                    if (which < 2) {
                        size_t base = (((size_t)b * HH + hh) * TT + t) * (HS / 2) + d / 2;
                        Cw[(size_t)which * BT * (CC / 2) + base] = f2h2(v0, v1);
                    } else {
                        __half* vt = (__half*)Caux;
                        size_t base = ((size_t)b * HH + hh) * HS;
                        vt[(base + d) * TT + t] = __float2half(v0);
                        vt[(base + d + 1) * TT + t] = __float2half(v1);
                    }
                } else if (OM == 2) {
                    Cw[(size_t)row * (N / 2) + c0 / 2] = f2h2(v0, v1);
                } else {
                    size_t oidx = (size_t)row * N + c0;
                    if (c0 + 1 < N) {
                        if (ACC) {
                            float2 old = *reinterpret_cast<float2*>(&Cf[oidx]);
                            v0 += old.x; v1 += old.y;
                        }
                        *reinterpret_cast<float2*>(&Cf[oidx]) = make_float2(v0, v1);
                    } else {
                        if (ACC) v0 += Cf[oidx];
                        Cf[oidx] = v0;
                    }
                }
            }
        }
    }
}

// ---------------- causal softmax: f32 in, packed fp16 out ----------------
__global__ void softmax_kernel(const float* __restrict__ att, uint32_t* __restrict__ att16) {
    int warp = threadIdx.x >> 5, lane = threadIdx.x & 31;
    size_t row = (size_t)blockIdx.x * 8 + warp;
    int qi = (int)(row % TT);
    const float* w = att + row * (size_t)TT;
    uint32_t* w16 = att16 + row * (size_t)(TT / 2);

    int i0 = lane * 4, i1 = 128 + lane * 4;
    float4 a0 = *reinterpret_cast<const float4*>(&w[i0]);
    float4 a1 = *reinterpret_cast<const float4*>(&w[i1]);
    float v[8] = {a0.x, a0.y, a0.z, a0.w, a1.x, a1.y, a1.z, a1.w};
    int base[2] = {i0, i1};

    float mx = -1e30f;
    #pragma unroll
    for (int h = 0; h < 2; h++)
        #pragma unroll
        for (int j = 0; j < 4; j++)
            if (base[h] + j <= qi) mx = fmaxf(mx, v[h * 4 + j]);
    #pragma unroll
    for (int s = 16; s > 0; s >>= 1) mx = fmaxf(mx, __shfl_xor_sync(0xffffffffu, mx, s));

    float e[8];
    float sum = 0.f;
    #pragma unroll
    for (int h = 0; h < 2; h++)
        #pragma unroll
        for (int j = 0; j < 4; j++) {
            int idx = h * 4 + j;
            e[idx] = (base[h] + j <= qi) ? expf(v[idx] - mx) : 0.f;
            sum += e[idx];
        }
    #pragma unroll
    for (int s = 16; s > 0; s >>= 1) sum += __shfl_xor_sync(0xffffffffu, sum, s);
    float inv = 1.f / sum;

    uint2 o0 = make_uint2(f2h2(e[0] * inv, e[1] * inv), f2h2(e[2] * inv, e[3] * inv));
    uint2 o1 = make_uint2(f2h2(e[4] * inv, e[5] * inv), f2h2(e[6] * inv, e[7] * inv));
    *reinterpret_cast<uint2*>(&w16[lane * 2]) = o0;
    *reinterpret_cast<uint2*>(&w16[64 + lane * 2]) = o1;
}

// ---------------- loss ----------------
__global__ void rowloss_kernel(const float* __restrict__ logits,
                               const int* __restrict__ targets,
                               float* __restrict__ rowloss) {
    int r = blockIdx.x;
    const float* lr = logits + (size_t)r * VV;
    int tid = threadIdx.x;
    __shared__ float red[256];
    __shared__ float s_mx;

    float mx = -1e30f;
    for (int c = tid; c < VV; c += 256) mx = fmaxf(mx, lr[c]);
    red[tid] = mx; __syncthreads();
    for (int st = 128; st > 0; st >>= 1) { if (tid < st) red[tid] = fmaxf(red[tid], red[tid + st]); __syncthreads(); }
    if (tid == 0) s_mx = red[0];
    __syncthreads();
    mx = s_mx;

    float s = 0.f;
    for (int c = tid; c < VV; c += 256) s += expf(lr[c] - mx);
    red[tid] = s; __syncthreads();
    for (int st = 128; st > 0; st >>= 1) { if (tid < st) red[tid] += red[tid + st]; __syncthreads(); }
    if (tid == 0) {
        int t = targets[r];
        rowloss[r] = -(lr[t] - mx - logf(red[0]));
    }
}

__global__ void lossreduce_kernel(const float* __restrict__ rowloss, float* __restrict__ out) {
    __shared__ float red[256];
    int tid = threadIdx.x;
    float s = 0.f;
    for (int r = tid; r < BT; r += 256) s += rowloss[r];
    red[tid] = s; __syncthreads();
    for (int st = 128; st > 0; st >>= 1) { if (tid < st) red[tid] += red[tid + st]; __syncthreads(); }
    if (tid == 0) out[0] = red[0] / BT;
}

// ---------------- host ----------------
static inline dim3 ggrid(int M, int N, int batch) {
    return dim3((N + 127) / 128, (M + 127) / 128, batch);
}

extern "C" void kernel_launch(void* const* d_in, const int* in_sizes, int n_in,
                              void* d_out, int out_size) {
    const int*   idx     = (const int*)  d_in[0];
    const int*   targets = (const int*)  d_in[1];
    const float* tok_emb = (const float*)d_in[2];
    const float* pos_emb = (const float*)d_in[3];
    const float* Wq      = (const float*)d_in[4];
    const float* Wk      = (const float*)d_in[5];
    const float* Wv      = (const float*)d_in[6];
    const float* Wproj   = (const float*)d_in[7];
    const float* bproj   = (const float*)d_in[8];
    const float* W1      = (const float*)d_in[9];
    const float* b1      = (const float*)d_in[10];
    const float* W2      = (const float*)d_in[11];
    const float* b2      = (const float*)d_in[12];
    const float* ln1_g   = (const float*)d_in[13];
    const float* ln1_b   = (const float*)d_in[14];
    const float* ln2_g   = (const float*)d_in[15];
    const float* ln2_b   = (const float*)d_in[16];
    const float* lnf_g   = (const float*)d_in[17];
    const float* lnf_b   = (const float*)d_in[18];
    const float* Wlm     = (const float*)d_in[19];
    const float* blm     = (const float*)d_in[20];
    float* out = (float*)d_out;

    float* x    = nullptr; cudaGetSymbolAddress((void**)&x,    g_x);
    uint32_t* h16  = nullptr; cudaGetSymbolAddress((void**)&h16,  g_h16);
    uint32_t* qk16 = nullptr; cudaGetSymbolAddress((void**)&qk16, g_qk16);
    uint32_t* v16t = nullptr; cudaGetSymbolAddress((void**)&v16t, g_v16t);
    float* att  = nullptr; cudaGetSymbolAddress((void**)&att,  g_att);
    uint32_t* att16 = nullptr; cudaGetSymbolAddress((void**)&att16, g_att16);
    uint32_t* a16  = nullptr; cudaGetSymbolAddress((void**)&a16,  g_a16);
    uint32_t* ff16 = nullptr; cudaGetSymbolAddress((void**)&ff16, g_ff16);
    float* rowloss = nullptr; cudaGetSymbolAddress((void**)&rowloss, g_rowloss);
    uint32_t* wqkv16  = nullptr; cudaGetSymbolAddress((void**)&wqkv16,  g_wqkv16);
    uint32_t* wproj16 = nullptr; cudaGetSymbolAddress((void**)&wproj16, g_wproj16);
    uint32_t* w116    = nullptr; cudaGetSymbolAddress((void**)&w116,    g_w116);
    uint32_t* w216    = nullptr; cudaGetSymbolAddress((void**)&w216,    g_w216);
    uint32_t* wlm16   = nullptr; cudaGetSymbolAddress((void**)&wlm16,   g_wlm16);

    const float rs = rsqrtf((float)HS);
    uint32_t* q16 = qk16;
    uint32_t* k16 = qk16 + (size_t)BT * (CC / 2);

    // kernel instantiations + dynamic smem opt-in
    auto kQKV  = gemm_tc<0, 0, false, false, false, 1>;
    auto kATT  = gemm_tc<0, 1, false, false, false, 0>;
    auto kAV   = gemm_tc<0, 1, false, false, false, 2>;
    auto kPROJ = gemm_tc<1, 0, true,  false, true,  0>;
    auto kFF1  = gemm_tc<0, 0, true,  true,  false, 2>;
    auto kFF2  = gemm_tc<0, 0, true,  false, true,  0>;
    auto kLM   = gemm_tc<0, 0, true,  false, false, 0>;
    cudaFuncSetAttribute(kQKV,  cudaFuncAttributeMaxDynamicSharedMemorySize, GDSM);
    cudaFuncSetAttribute(kATT,  cudaFuncAttributeMaxDynamicSharedMemorySize, GDSM);
    cudaFuncSetAttribute(kAV,   cudaFuncAttributeMaxDynamicSharedMemorySize, GDSM);
    cudaFuncSetAttribute(kPROJ, cudaFuncAttributeMaxDynamicSharedMemorySize, GDSM);
    cudaFuncSetAttribute(kFF1,  cudaFuncAttributeMaxDynamicSharedMemorySize, GDSM);
    cudaFuncSetAttribute(kFF2,  cudaFuncAttributeMaxDynamicSharedMemorySize, GDSM);
    cudaFuncSetAttribute(kLM,   cudaFuncAttributeMaxDynamicSharedMemorySize, GDSM);

    // ---- pack weights ----
    {
        size_t n;
        n = (size_t)LL * (CC / 2) * (3 * CC);
        pack_qkv_kernel<<<(unsigned)((n + 255) / 256), 256>>>(Wq, Wk, Wv, wqkv16);
        n = (size_t)LL * (CC / 2) * CC;
        pack_w_kernel<<<(unsigned)((n + 255) / 256), 256>>>(Wproj, wproj16, LL * CC / 2, CC, CC);
        n = (size_t)LL * (CC / 2) * FFD;
        pack_w_kernel<<<(unsigned)((n + 255) / 256), 256>>>(W1, w116, LL * CC / 2, FFD, FFD);
        n = (size_t)LL * (FFD / 2) * CC;
        pack_w_kernel<<<(unsigned)((n + 255) / 256), 256>>>(W2, w216, LL * FFD / 2, CC, CC);
        n = (size_t)(CC / 2) * VVP;
        pack_w_kernel<<<(unsigned)((n + 255) / 256), 256>>>(Wlm, wlm16, CC / 2, VV, VVP);
    }

    embed_kernel<<<(BT * CC + 255) / 256, 256>>>(idx, tok_emb, pos_emb, x);

    for (int l = 0; l < LL; l++) {
        const uint32_t* wqkv = wqkv16 + (size_t)l * (CC / 2) * (3 * CC);
        const uint32_t* wp   = wproj16 + (size_t)l * (CC / 2) * CC;
        const uint32_t* w1   = w116 + (size_t)l * (CC / 2) * FFD;
        const uint32_t* w2   = w216 + (size_t)l * (FFD / 2) * CC;
        const float* bp  = bproj + (size_t)l * CC;
        const float* bb1 = b1 + (size_t)l * FFD;
        const float* bb2 = b2 + (size_t)l * CC;

        ln_kernel<<<BT, 256>>>(x, ln1_g + (size_t)l * CC, ln1_b + (size_t)l * CC, h16);

        // fused QKV: q16|k16 packed, v -> v16t transposed halves
        kQKV<<<ggrid(BT, 3 * CC, 1), 256, GDSM>>>(
            h16, wqkv, nullptr, qk16, v16t, BT, 3 * CC, 3 * CC, CC, 1.f, 0, 0, 0);

        // scores = Q @ K^T * rs (batched over B*H)
        kATT<<<ggrid(TT, TT, BB * HH), 256, GDSM>>>(
            q16, k16, nullptr, att, nullptr, TT, TT, TT, HS, rs,
            (size_t)TT * (HS / 2), (size_t)TT * (HS / 2), (size_t)TT * TT);

        softmax_kernel<<<BB * HH * TT / 8, 256>>>(att, att16);

        // A = softmax @ V (batched): B = v16t transposed-packed [HS][TT/2]
        kAV<<<ggrid(TT, HS, BB * HH), 256, GDSM>>>(
            att16, v16t, nullptr, a16, nullptr, TT, HS, HS, TT, 1.f,
            (size_t)TT * (TT / 2), (size_t)HS * (TT / 2), (size_t)TT * (HS / 2));

        // x += attn_out @ Wproj + bproj
        kPROJ<<<ggrid(BT, CC, 1), 256, GDSM>>>(
            a16, wp, bp, x, nullptr, BT, CC, CC, CC, 1.f, 0, 0, 0);

        ln_kernel<<<BT, 256>>>(x, ln2_g + (size_t)l * CC, ln2_b + (size_t)l * CC, h16);

        // ff16 = relu(h @ W1 + b1)
        kFF1<<<ggrid(BT, FFD, 1), 256, GDSM>>>(
            h16, w1, bb1, ff16, nullptr, BT, FFD, FFD, CC, 1.f, 0, 0, 0);

        // x += ff @ W2 + b2
        kFF2<<<ggrid(BT, CC, 1), 256, GDSM>>>(
            ff16, w2, bb2, x, nullptr, BT, CC, CC, FFD, 1.f, 0, 0, 0);
    }

    ln_kernel<<<BT, 256>>>(x, lnf_g, lnf_b, h16);

    // logits = h @ Wlm + blm
    kLM<<<ggrid(BT, VVP, 1), 256, GDSM>>>(
        h16, wlm16, blm, out, nullptr, BT, VV, VVP, CC, 1.f, 0, 0, 0);

    rowloss_kernel<<<BT, 256>>>(out, targets, rowloss);
    if ((long long)out_size > (long long)BT * VV) {
        lossreduce_kernel<<<1, 256>>>(rowloss, out + (size_t)BT * VV);
    }
}

// round 14
// speedup vs baseline: 2.5349x; 1.0638x over previous
#include <cuda_runtime.h>
#include <cuda_fp16.h>
#include <math.h>
#include <stdint.h>

// ---------------- problem constants ----------------
constexpr int BB = 32, TT = 256, VV = 30522, CC = 768, HH = 8, LL = 10;
constexpr int HS = CC / HH;     // 96
constexpr int FFD = 4 * CC;     // 3072
constexpr int BT = BB * TT;     // 8192
constexpr int VVP = 30592;      // VV padded to multiple of 128
constexpr float LN_EPS = 1e-5f;

// ---------------- scratch ----------------
__device__ float g_x[BT * CC];                       // residual (f32)
__device__ uint32_t g_h16[BT * CC / 2];              // LN out (interleaved pairs)
__device__ uint32_t g_qk16[BT * CC];                 // q | k packed (interleaved)
__device__ uint32_t g_v16t[BT * CC / 2 + 4096];      // V [B,H,HS,T] halves (interleaved words)
__device__ float g_att[(size_t)BB * HH * TT * TT];   // scores f32
__device__ uint32_t g_att16[(size_t)BB * HH * TT * TT / 2];  // interleaved
__device__ uint32_t g_a16[BT * CC / 2];              // attn out (interleaved)
__device__ uint32_t g_ff16[(size_t)BT * FFD / 2];    // interleaved
__device__ float g_rowloss[BT];
// pre-packed fp16 weights (k-major, NOT interleaved): [K/2][N]
__device__ uint32_t g_wqkv16[(size_t)LL * (CC / 2) * (3 * CC)];
__device__ uint32_t g_wproj16[(size_t)LL * (CC / 2) * CC];
__device__ uint32_t g_w116[(size_t)LL * (CC / 2) * FFD];
__device__ uint32_t g_w216[(size_t)LL * (FFD / 2) * CC];
__device__ uint32_t g_wlm16[(size_t)(CC / 2) * VVP];

// fragment-order interleave: within each group of 8 half2-words,
// semantic word w goes to position ((w&3)<<1)|((w>>2)&1).
// Consumer then finds pairs (cq, cq+4) at adjacent positions (2cq, 2cq+1).
__device__ __forceinline__ int ilv(int w) {
    return (w & ~7) | ((w & 3) << 1) | ((w >> 2) & 1);
}

__device__ __forceinline__ uint32_t f2h2(float lo, float hi) {
    uint32_t r;
    asm("{ .reg .f16 a, b; cvt.rn.f16.f32 a, %1; cvt.rn.f16.f32 b, %2; mov.b32 %0, {a, b}; }"
        : "=r"(r) : "f"(lo), "f"(hi));
    return r;
}

__device__ __forceinline__ void mma_fp16(float d[4], const uint32_t a[4], const uint32_t b[2]) {
    asm volatile(
        "mma.sync.aligned.m16n8k16.row.col.f32.f16.f16.f32 "
        "{%0,%1,%2,%3}, {%4,%5,%6,%7}, {%8,%9}, {%0,%1,%2,%3};\n"
        : "+f"(d[0]), "+f"(d[1]), "+f"(d[2]), "+f"(d[3])
        : "r"(a[0]), "r"(a[1]), "r"(a[2]), "r"(a[3]), "r"(b[0]), "r"(b[1]));
}

__device__ __forceinline__ void cp16(uint32_t dst, const void* src) {
    asm volatile("cp.async.cg.shared.global [%0], [%1], 16;" :: "r"(dst), "l"(src) : "memory");
}

// ---------------- weight packing (k-major, plain order) ----------------
__global__ void pack_w_kernel(const float* __restrict__ W, uint32_t* __restrict__ out,
                              int K2tot, int N, int Nb) {
    size_t i = (size_t)blockIdx.x * blockDim.x + threadIdx.x;
    if (i >= (size_t)K2tot * Nb) return;
    int k2 = (int)(i / Nb), n = (int)(i % Nb);
    float lo = 0.f, hi = 0.f;
    if (n < N) {
        lo = W[(size_t)(2 * k2) * N + n];
        hi = W[(size_t)(2 * k2 + 1) * N + n];
    }
    out[i] = f2h2(lo, hi);
}

__global__ void pack_qkv_kernel(const float* __restrict__ Wq, const float* __restrict__ Wk,
                                const float* __restrict__ Wv, uint32_t* __restrict__ out) {
    size_t i = (size_t)blockIdx.x * blockDim.x + threadIdx.x;
    const size_t total = (size_t)LL * (CC / 2) * (3 * CC);
    if (i >= total) return;
    int n = (int)(i % (3 * CC));
    size_t rest = i / (3 * CC);
    int k2 = (int)(rest % (CC / 2));
    int l = (int)(rest / (CC / 2));
    int which = n / CC, nn = n % CC;
    const float* W = (which == 0) ? Wq : (which == 1) ? Wk : Wv;
    const float* base = W + (size_t)l * CC * CC;
    out[i] = f2h2(base[(size_t)(2 * k2) * CC + nn], base[(size_t)(2 * k2 + 1) * CC + nn]);
}

// ---------------- embedding ----------------
__global__ void embed_kernel(const int* __restrict__ idx,
                             const float* __restrict__ tok,
                             const float* __restrict__ pos,
                             float* __restrict__ x) {
    int i = blockIdx.x * blockDim.x + threadIdx.x;
    if (i >= BT * CC) return;
    int bt = i / CC, c = i % CC;
    int t = bt % TT;
    x[i] = tok[(size_t)idx[bt] * CC + c] + pos[(size_t)t * CC + c];
}

// ---------------- layernorm -> packed fp16 (interleaved) ----------------
__global__ void ln_kernel(const float* __restrict__ x,
                          const float* __restrict__ g,
                          const float* __restrict__ b,
                          uint32_t* __restrict__ out16) {
    int row = blockIdx.x;
    const float* xr = x + (size_t)row * CC;
    uint32_t* orow = out16 + (size_t)row * (CC / 2);
    __shared__ float red[256];
    __shared__ float s_mu, s_inv;
    int tid = threadIdx.x;

    float s = 0.f;
    for (int c = tid; c < CC; c += 256) s += xr[c];
    red[tid] = s; __syncthreads();
    for (int st = 128; st > 0; st >>= 1) { if (tid < st) red[tid] += red[tid + st]; __syncthreads(); }
    if (tid == 0) s_mu = red[0] / CC;
    __syncthreads();
    float mu = s_mu;

    float v = 0.f;
    for (int c = tid; c < CC; c += 256) { float d = xr[c] - mu; v += d * d; }
    red[tid] = v; __syncthreads();
    for (int st = 128; st > 0; st >>= 1) { if (tid < st) red[tid] += red[tid + st]; __syncthreads(); }
    if (tid == 0) s_inv = rsqrtf(red[0] / CC + LN_EPS);
    __syncthreads();
    float inv = s_inv;

    for (int c2 = tid; c2 < CC / 2; c2 += 256) {
        int c = 2 * c2;
        float v0 = (xr[c] - mu) * inv * g[c] + b[c];
        float v1 = (xr[c + 1] - mu) * inv * g[c + 1] + b[c + 1];
        orow[ilv(c2)] = f2h2(v0, v1);
    }
}

// ---------------- fp16 GEMM, cp.async 4-stage, 128x128x32 m16n8k16 ----------------
// A: interleaved packed pairs. AM 0 = flat [row][K/2]; 1 = gather [B,H,T,HS/2]
// B: BMo 0 = k-major weights [K/2][Nb] (plain order); 1 = n-major interleaved [n][K/2]
// Out: OM 0 = f32; 1 = QKV scatter (q/k interleaved, v -> v16t); 2 = interleaved pairs
constexpr int GNS = 4;
constexpr int GAW = 128 * 24;             // A stage words (stride 24)
constexpr int GBW = 128 * 24;             // B stage words (covers 16*136=2176 too)
constexpr int GSTW = GAW + GBW;
constexpr int GDSM = GNS * GSTW * 4;      // 98304 bytes

template<int AM, int BMo, bool BIAS, bool RELU, bool ACC, int OM>
__global__ __launch_bounds__(256, 2)
void gemm_tc(const uint32_t* __restrict__ A, const uint32_t* __restrict__ Bw,
             const float* __restrict__ bias, void* __restrict__ Cmv,
             void* __restrict__ Caux,
             int M, int N, int Nb, int K, float alpha,
             size_t sA, size_t sB, size_t sC) {
    constexpr int BK = 32;
    extern __shared__ __align__(16) uint32_t smw[];
    uint32_t smb = (uint32_t)__cvta_generic_to_shared(smw);

    const uint32_t* Ab = A + (size_t)blockIdx.z * sA;
    const uint32_t* Bb = Bw + ((BMo == 1) ? (size_t)blockIdx.z * sB : 0);

    int bm = blockIdx.y * 128;
    int bn = blockIdx.x * 128;
    int tid = threadIdx.x;
    int wid = tid >> 5, lane = tid & 31;
    int wm = (wid & 1) * 64;
    int wn = (wid >> 1) * 32;
    int gq = lane >> 2;
    int cq = lane & 3;

    const int nIter = K / BK;

    float acc[4][4][4];
    #pragma unroll
    for (int i = 0; i < 4; i++)
        #pragma unroll
        for (int j = 0; j < 4; j++)
            #pragma unroll
            for (int t = 0; t < 4; t++) acc[i][j][t] = 0.f;

    auto issue_stage = [&](int it) {
        if (it < nIter) {
            int k0 = it * BK;
            int st = it & (GNS - 1);
            uint32_t abase = smb + (uint32_t)(st * GSTW) * 4;
            uint32_t bbase = abase + GAW * 4;
            #pragma unroll
            for (int r = 0; r < 2; r++) {
                int id = tid + r * 256;
                {   // A chunk: 4 consecutive words (positions; content pre-interleaved)
                    int m = id >> 2, k2q = (id & 3) * 4;
                    int row = bm + m;
                    const uint32_t* g;
                    if (AM == 0) {
                        g = Ab + (size_t)row * (K / 2) + (k0 / 2 + k2q);
                    } else {
                        int k = k0 + 2 * k2q;        // chunk never straddles a head
                        int b = row / TT, t = row % TT, hh = k / HS, d = k % HS;
                        g = Ab + (((size_t)b * HH + hh) * TT + t) * (HS / 2) + d / 2;
                    }
                    cp16(abase + (uint32_t)(m * 24 + k2q) * 4, g);
                }
                if (BMo == 0) {
                    int k2 = id >> 5, n4 = (id & 31) * 4;
                    const uint32_t* g = Bb + (size_t)(k0 / 2 + k2) * Nb + bn + n4;
                    cp16(bbase + (uint32_t)(k2 * 136 + n4) * 4, g);
                } else {
                    int n = id >> 2, k2q = (id & 3) * 4;
                    const uint32_t* g = Bb + (size_t)(bn + n) * (K / 2) + (k0 / 2 + k2q);
                    cp16(bbase + (uint32_t)(n * 24 + k2q) * 4, g);
                }
            }
        }
        asm volatile("cp.async.commit_group;" ::: "memory");
    };

    #pragma unroll
    for (int s = 0; s < GNS - 1; s++) issue_stage(s);

    for (int it = 0; it < nIter; ++it) {
        asm volatile("cp.async.wait_group 2;" ::: "memory");
        __syncthreads();
        issue_stage(it + GNS - 1);

        const uint32_t* As_ = smw + (it & (GNS - 1)) * GSTW;
        const uint32_t* Bs_ = As_ + GAW;

        #pragma unroll
        for (int kk2 = 0; kk2 < BK / 2; kk2 += 8) {
            uint32_t af[4][4];
            uint32_t bf[4][2];
            #pragma unroll
            for (int i = 0; i < 4; i++) {
                int mr = wm + i * 16;
                uint2 lo = *reinterpret_cast<const uint2*>(&As_[(mr + gq) * 24 + kk2 + 2 * cq]);
                uint2 hi = *reinterpret_cast<const uint2*>(&As_[(mr + gq + 8) * 24 + kk2 + 2 * cq]);
                af[i][0] = lo.x; af[i][2] = lo.y;
                af[i][1] = hi.x; af[i][3] = hi.y;
            }
            #pragma unroll
            for (int j = 0; j < 4; j++) {
                int nc = wn + j * 8 + gq;
                if (BMo == 0) {
                    bf[j][0] = Bs_[(kk2 + cq) * 136 + nc];
                    bf[j][1] = Bs_[(kk2 + cq + 4) * 136 + nc];
                } else {
                    uint2 bv = *reinterpret_cast<const uint2*>(&Bs_[nc * 24 + kk2 + 2 * cq]);
                    bf[j][0] = bv.x; bf[j][1] = bv.y;
                }
            }
            #pragma unroll
            for (int i = 0; i < 4; i++)
                #pragma unroll
                for (int j = 0; j < 4; j++)
                    mma_fp16(acc[i][j], af[i], bf[j]);
        }
    }

    // epilogue
    float* Cf = (float*)Cmv + ((OM == 0) ? (size_t)blockIdx.z * sC : 0);
    uint32_t* Cw = (uint32_t*)Cmv + ((OM == 2) ? (size_t)blockIdx.z * sC : 0);

    #pragma unroll
    for (int i = 0; i < 4; i++) {
        int r0 = bm + wm + i * 16 + gq;
        #pragma unroll
        for (int j = 0; j < 4; j++) {
            int c0 = bn + wn + j * 8 + cq * 2;
            if (c0 >= N) continue;
            #pragma unroll
            for (int half = 0; half < 2; half++) {
                int row = r0 + half * 8;
                float v0 = acc[i][j][half * 2 + 0] * alpha;
                float v1 = acc[i][j][half * 2 + 1] * alpha;
                if (BIAS) { v0 += bias[c0]; v1 += (c0 + 1 < N) ? bias[c0 + 1] : 0.f; }
                if (RELU) { v0 = fmaxf(v0, 0.f); v1 = fmaxf(v1, 0.f); }

                if (OM == 1) {
                    int which = c0 / CC, cc = c0 % CC;
                    int b = row / TT, t = row % TT, hh = cc / HS, d = cc % HS;
                    if (which < 2) {
                        size_t base = (((size_t)b * HH + hh) * TT + t) * (HS / 2) + ilv(d / 2);
                        Cw[(size_t)which * BT * (CC / 2) + base] = f2h2(v0, v1);
                    } else {
                        __half* vt = (__half*)Caux;
                        size_t base = ((size_t)b * HH + hh) * HS;
                        int hpos = ilv(t >> 1) * 2 + (t & 1);
                        vt[(base + d) * TT + hpos] = __float2half(v0);
                        vt[(base + d + 1) * TT + hpos] = __float2half(v1);
                    }
                } else if (OM == 2) {
                    Cw[(size_t)row * (N / 2) + ilv(c0 / 2)] = f2h2(v0, v1);
                } else {
                    size_t oidx = (size_t)row * N + c0;
                    if (c0 + 1 < N) {
                        if (ACC) {
                            float2 old = *reinterpret_cast<float2*>(&Cf[oidx]);
                            v0 += old.x; v1 += old.y;
                        }
                        *reinterpret_cast<float2*>(&Cf[oidx]) = make_float2(v0, v1);
                    } else {
                        if (ACC) v0 += Cf[oidx];
                        Cf[oidx] = v0;
                    }
                }
            }
        }
    }
}

// ---------------- causal softmax: f32 in, interleaved packed fp16 out ----------------
__global__ void softmax_kernel(const float* __restrict__ att, uint32_t* __restrict__ att16) {
    int warp = threadIdx.x >> 5, lane = threadIdx.x & 31;
    size_t row = (size_t)blockIdx.x * 8 + warp;
    int qi = (int)(row % TT);
    const float* w = att + row * (size_t)TT;
    uint32_t* w16 = att16 + row * (size_t)(TT / 2);

    int i0 = lane * 4, i1 = 128 + lane * 4;
    float4 a0 = *reinterpret_cast<const float4*>(&w[i0]);
    float4 a1 = *reinterpret_cast<const float4*>(&w[i1]);
    float v[8] = {a0.x, a0.y, a0.z, a0.w, a1.x, a1.y, a1.z, a1.w};
    int base[2] = {i0, i1};

    float mx = -1e30f;
    #pragma unroll
    for (int h = 0; h < 2; h++)
        #pragma unroll
        for (int j = 0; j < 4; j++)
            if (base[h] + j <= qi) mx = fmaxf(mx, v[h * 4 + j]);
    #pragma unroll
    for (int s = 16; s > 0; s >>= 1) mx = fmaxf(mx, __shfl_xor_sync(0xffffffffu, mx, s));

    float e[8];
    float sum = 0.f;
    #pragma unroll
    for (int h = 0; h < 2; h++)
        #pragma unroll
        for (int j = 0; j < 4; j++) {
            int idx = h * 4 + j;
            e[idx] = (base[h] + j <= qi) ? expf(v[idx] - mx) : 0.f;
            sum += e[idx];
        }
    #pragma unroll
    for (int s = 16; s > 0; s >>= 1) sum += __shfl_xor_sync(0xffffffffu, sum, s);
    float inv = 1.f / sum;

    w16[ilv(lane * 2)]      = f2h2(e[0] * inv, e[1] * inv);
    w16[ilv(lane * 2 + 1)]  = f2h2(e[2] * inv, e[3] * inv);
    w16[ilv(64 + lane * 2)]     = f2h2(e[4] * inv, e[5] * inv);
    w16[ilv(64 + lane * 2 + 1)] = f2h2(e[6] * inv, e[7] * inv);
}

// ---------------- loss ----------------
__global__ void rowloss_kernel(const float* __restrict__ logits,
                               const int* __restrict__ targets,
                               float* __restrict__ rowloss) {
    int r = blockIdx.x;
    const float* lr = logits + (size_t)r * VV;
    int tid = threadIdx.x;
    __shared__ float red[256];
    __shared__ float s_mx;

    float mx = -1e30f;
    for (int c = tid; c < VV; c += 256) mx = fmaxf(mx, lr[c]);
    red[tid] = mx; __syncthreads();
    for (int st = 128; st > 0; st >>= 1) { if (tid < st) red[tid] = fmaxf(red[tid], red[tid + st]); __syncthreads(); }
    if (tid == 0) s_mx = red[0];
    __syncthreads();
    mx = s_mx;

    float s = 0.f;
    for (int c = tid; c < VV; c += 256) s += expf(lr[c] - mx);
    red[tid] = s; __syncthreads();
    for (int st = 128; st > 0; st >>= 1) { if (tid < st) red[tid] += red[tid + st]; __syncthreads(); }
    if (tid == 0) {
        int t = targets[r];
        rowloss[r] = -(lr[t] - mx - logf(red[0]));
    }
}

__global__ void lossreduce_kernel(const float* __restrict__ rowloss, float* __restrict__ out) {
    __shared__ float red[256];
    int tid = threadIdx.x;
    float s = 0.f;
    for (int r = tid; r < BT; r += 256) s += rowloss[r];
    red[tid] = s; __syncthreads();
    for (int st = 128; st > 0; st >>= 1) { if (tid < st) red[tid] += red[tid + st]; __syncthreads(); }
    if (tid == 0) out[0] = red[0] / BT;
}

// ---------------- host ----------------
static inline dim3 ggrid(int M, int N, int batch) {
    return dim3((N + 127) / 128, (M + 127) / 128, batch);
}

extern "C" void kernel_launch(void* const* d_in, const int* in_sizes, int n_in,
                              void* d_out, int out_size) {
    const int*   idx     = (const int*)  d_in[0];
    const int*   targets = (const int*)  d_in[1];
    const float* tok_emb = (const float*)d_in[2];
    const float* pos_emb = (const float*)d_in[3];
    const float* Wq      = (const float*)d_in[4];
    const float* Wk      = (const float*)d_in[5];
    const float* Wv      = (const float*)d_in[6];
    const float* Wproj   = (const float*)d_in[7];
    const float* bproj   = (const float*)d_in[8];
    const float* W1      = (const float*)d_in[9];
    const float* b1      = (const float*)d_in[10];
    const float* W2      = (const float*)d_in[11];
    const float* b2      = (const float*)d_in[12];
    const float* ln1_g   = (const float*)d_in[13];
    const float* ln1_b   = (const float*)d_in[14];
    const float* ln2_g   = (const float*)d_in[15];
    const float* ln2_b   = (const float*)d_in[16];
    const float* lnf_g   = (const float*)d_in[17];
    const float* lnf_b   = (const float*)d_in[18];
    const float* Wlm     = (const float*)d_in[19];
    const float* blm     = (const float*)d_in[20];
    float* out = (float*)d_out;

    float* x    = nullptr; cudaGetSymbolAddress((void**)&x,    g_x);
    uint32_t* h16  = nullptr; cudaGetSymbolAddress((void**)&h16,  g_h16);
    uint32_t* qk16 = nullptr; cudaGetSymbolAddress((void**)&qk16, g_qk16);
    uint32_t* v16t = nullptr; cudaGetSymbolAddress((void**)&v16t, g_v16t);
    float* att  = nullptr; cudaGetSymbolAddress((void**)&att,  g_att);
    uint32_t* att16 = nullptr; cudaGetSymbolAddress((void**)&att16, g_att16);
    uint32_t* a16  = nullptr; cudaGetSymbolAddress((void**)&a16,  g_a16);
    uint32_t* ff16 = nullptr; cudaGetSymbolAddress((void**)&ff16, g_ff16);
    float* rowloss = nullptr; cudaGetSymbolAddress((void**)&rowloss, g_rowloss);
    uint32_t* wqkv16  = nullptr; cudaGetSymbolAddress((void**)&wqkv16,  g_wqkv16);
    uint32_t* wproj16 = nullptr; cudaGetSymbolAddress((void**)&wproj16, g_wproj16);
    uint32_t* w116    = nullptr; cudaGetSymbolAddress((void**)&w116,    g_w116);
    uint32_t* w216    = nullptr; cudaGetSymbolAddress((void**)&w216,    g_w216);
    uint32_t* wlm16   = nullptr; cudaGetSymbolAddress((void**)&wlm16,   g_wlm16);

    const float rs = rsqrtf((float)HS);
    uint32_t* q16 = qk16;
    uint32_t* k16 = qk16 + (size_t)BT * (CC / 2);

    auto kQKV  = gemm_tc<0, 0, false, false, false, 1>;
    auto kATT  = gemm_tc<0, 1, false, false, false, 0>;
    auto kAV   = gemm_tc<0, 1, false, false, false, 2>;
    auto kPROJ = gemm_tc<1, 0, true,  false, true,  0>;
    auto kFF1  = gemm_tc<0, 0, true,  true,  false, 2>;
    auto kFF2  = gemm_tc<0, 0, true,  false, true,  0>;
    auto kLM   = gemm_tc<0, 0, true,  false, false, 0>;
    cudaFuncSetAttribute(kQKV,  cudaFuncAttributeMaxDynamicSharedMemorySize, GDSM);
    cudaFuncSetAttribute(kATT,  cudaFuncAttributeMaxDynamicSharedMemorySize, GDSM);
    cudaFuncSetAttribute(kAV,   cudaFuncAttributeMaxDynamicSharedMemorySize, GDSM);
    cudaFuncSetAttribute(kPROJ, cudaFuncAttributeMaxDynamicSharedMemorySize, GDSM);
    cudaFuncSetAttribute(kFF1,  cudaFuncAttributeMaxDynamicSharedMemorySize, GDSM);
    cudaFuncSetAttribute(kFF2,  cudaFuncAttributeMaxDynamicSharedMemorySize, GDSM);
    cudaFuncSetAttribute(kLM,   cudaFuncAttributeMaxDynamicSharedMemorySize, GDSM);

    // ---- pack weights ----
    {
        size_t n;
        n = (size_t)LL * (CC / 2) * (3 * CC);
        pack_qkv_kernel<<<(unsigned)((n + 255) / 256), 256>>>(Wq, Wk, Wv, wqkv16);
        n = (size_t)LL * (CC / 2) * CC;
        pack_w_kernel<<<(unsigned)((n + 255) / 256), 256>>>(Wproj, wproj16, LL * CC / 2, CC, CC);
        n = (size_t)LL * (CC / 2) * FFD;
        pack_w_kernel<<<(unsigned)((n + 255) / 256), 256>>>(W1, w116, LL * CC / 2, FFD, FFD);
        n = (size_t)LL * (FFD / 2) * CC;
        pack_w_kernel<<<(unsigned)((n + 255) / 256), 256>>>(W2, w216, LL * FFD / 2, CC, CC);
        n = (size_t)(CC / 2) * VVP;
        pack_w_kernel<<<(unsigned)((n + 255) / 256), 256>>>(Wlm, wlm16, CC / 2, VV, VVP);
    }

    embed_kernel<<<(BT * CC + 255) / 256, 256>>>(idx, tok_emb, pos_emb, x);

    for (int l = 0; l < LL; l++) {
        const uint32_t* wqkv = wqkv16 + (size_t)l * (CC / 2) * (3 * CC);
        const uint32_t* wp   = wproj16 + (size_t)l * (CC / 2) * CC;
        const uint32_t* w1   = w116 + (size_t)l * (CC / 2) * FFD;
        const uint32_t* w2   = w216 + (size_t)l * (FFD / 2) * CC;
        const float* bp  = bproj + (size_t)l * CC;
        const float* bb1 = b1 + (size_t)l * FFD;
        const float* bb2 = b2 + (size_t)l * CC;

        ln_kernel<<<BT, 256>>>(x, ln1_g + (size_t)l * CC, ln1_b + (size_t)l * CC, h16);

        kQKV<<<ggrid(BT, 3 * CC, 1), 256, GDSM>>>(
            h16, wqkv, nullptr, qk16, v16t, BT, 3 * CC, 3 * CC, CC, 1.f, 0, 0, 0);

        kATT<<<ggrid(TT, TT, BB * HH), 256, GDSM>>>(
            q16, k16, nullptr, att, nullptr, TT, TT, TT, HS, rs,
            (size_t)TT * (HS / 2), (size_t)TT * (HS / 2), (size_t)TT * TT);

        softmax_kernel<<<BB * HH * TT / 8, 256>>>(att, att16);

        kAV<<<ggrid(TT, HS, BB * HH), 256, GDSM>>>(
            att16, v16t, nullptr, a16, nullptr, TT, HS, HS, TT, 1.f,
            (size_t)TT * (TT / 2), (size_t)HS * (TT / 2), (size_t)TT * (HS / 2));

        kPROJ<<<ggrid(BT, CC, 1), 256, GDSM>>>(
            a16, wp, bp, x, nullptr, BT, CC, CC, CC, 1.f, 0, 0, 0);

        ln_kernel<<<BT, 256>>>(x, ln2_g + (size_t)l * CC, ln2_b + (size_t)l * CC, h16);

        kFF1<<<ggrid(BT, FFD, 1), 256, GDSM>>>(
            h16, w1, bb1, ff16, nullptr, BT, FFD, FFD, CC, 1.f, 0, 0, 0);

        kFF2<<<ggrid(BT, CC, 1), 256, GDSM>>>(
            ff16, w2, bb2, x, nullptr, BT, CC, CC, FFD, 1.f, 0, 0, 0);
    }

    ln_kernel<<<BT, 256>>>(x, lnf_g, lnf_b, h16);

    kLM<<<ggrid(BT, VVP, 1), 256, GDSM>>>(
        h16, wlm16, blm, out, nullptr, BT, VV, VVP, CC, 1.f, 0, 0, 0);

    rowloss_kernel<<<BT, 256>>>(out, targets, rowloss);
    if ((long long)out_size > (long long)BT * VV) {
        lossreduce_kernel<<<1, 256>>>(rowloss, out + (size_t)BT * VV);
    }
}

// round 17
// speedup vs baseline: 2.5366x; 1.0007x over previous
#include <cuda_runtime.h>
#include <cuda_fp16.h>
#include <math.h>
#include <stdint.h>

// ---------------- problem constants ----------------
constexpr int BB = 32, TT = 256, VV = 30522, CC = 768, HH = 8, LL = 10;
constexpr int HS = CC / HH;     // 96
constexpr int FFD = 4 * CC;     // 3072
constexpr int BT = BB * TT;     // 8192
constexpr int VVP = 30592;      // VV padded to multiple of 128
constexpr float LN_EPS = 1e-5f;

// ---------------- scratch ----------------
__device__ float g_x[BT * CC];                       // residual (f32)
__device__ uint32_t g_h16[BT * CC / 2];              // LN out (interleaved pairs)
__device__ uint32_t g_qk16[BT * CC];                 // q | k packed (interleaved)
__device__ uint32_t g_v16t[BT * CC / 2 + 4096];      // V [B,H,HS,T] halves (interleaved words)
__device__ uint32_t g_att16[(size_t)BB * HH * TT * TT / 2];  // softmax out (interleaved)
__device__ uint32_t g_a16[BT * CC / 2];              // attn out (interleaved)
__device__ uint32_t g_ff16[(size_t)BT * FFD / 2];    // interleaved
__device__ float g_rowloss[BT];
// pre-packed fp16 weights (k-major, plain order): [K/2][N]
__device__ uint32_t g_wqkv16[(size_t)LL * (CC / 2) * (3 * CC)];
__device__ uint32_t g_wproj16[(size_t)LL * (CC / 2) * CC];
__device__ uint32_t g_w116[(size_t)LL * (CC / 2) * FFD];
__device__ uint32_t g_w216[(size_t)LL * (FFD / 2) * CC];
__device__ uint32_t g_wlm16[(size_t)(CC / 2) * VVP];

// fragment-order interleave within each group of 8 half2-words
__device__ __forceinline__ int ilv(int w) {
    return (w & ~7) | ((w & 3) << 1) | ((w >> 2) & 1);
}

__device__ __forceinline__ uint32_t f2h2(float lo, float hi) {
    uint32_t r;
    asm("{ .reg .f16 a, b; cvt.rn.f16.f32 a, %1; cvt.rn.f16.f32 b, %2; mov.b32 %0, {a, b}; }"
        : "=r"(r) : "f"(lo), "f"(hi));
    return r;
}

__device__ __forceinline__ void mma_fp16(float d[4], const uint32_t a[4], const uint32_t b[2]) {
    asm volatile(
        "mma.sync.aligned.m16n8k16.row.col.f32.f16.f16.f32 "
        "{%0,%1,%2,%3}, {%4,%5,%6,%7}, {%8,%9}, {%0,%1,%2,%3};\n"
        : "+f"(d[0]), "+f"(d[1]), "+f"(d[2]), "+f"(d[3])
        : "r"(a[0]), "r"(a[1]), "r"(a[2]), "r"(a[3]), "r"(b[0]), "r"(b[1]));
}

__device__ __forceinline__ void cp16(uint32_t dst, const void* src) {
    asm volatile("cp.async.cg.shared.global [%0], [%1], 16;" :: "r"(dst), "l"(src) : "memory");
}

// ---------------- weight packing ----------------
__global__ void pack_w_kernel(const float* __restrict__ W, uint32_t* __restrict__ out,
                              int K2tot, int N, int Nb) {
    size_t i = (size_t)blockIdx.x * blockDim.x + threadIdx.x;
    if (i >= (size_t)K2tot * Nb) return;
    int k2 = (int)(i / Nb), n = (int)(i % Nb);
    float lo = 0.f, hi = 0.f;
    if (n < N) {
        lo = W[(size_t)(2 * k2) * N + n];
        hi = W[(size_t)(2 * k2 + 1) * N + n];
    }
    out[i] = f2h2(lo, hi);
}

__global__ void pack_qkv_kernel(const float* __restrict__ Wq, const float* __restrict__ Wk,
                                const float* __restrict__ Wv, uint32_t* __restrict__ out) {
    size_t i = (size_t)blockIdx.x * blockDim.x + threadIdx.x;
    const size_t total = (size_t)LL * (CC / 2) * (3 * CC);
    if (i >= total) return;
    int n = (int)(i % (3 * CC));
    size_t rest = i / (3 * CC);
    int k2 = (int)(rest % (CC / 2));
    int l = (int)(rest / (CC / 2));
    int which = n / CC, nn = n % CC;
    const float* W = (which == 0) ? Wq : (which == 1) ? Wk : Wv;
    const float* base = W + (size_t)l * CC * CC;
    out[i] = f2h2(base[(size_t)(2 * k2) * CC + nn], base[(size_t)(2 * k2 + 1) * CC + nn]);
}

// ---------------- embedding ----------------
__global__ void embed_kernel(const int* __restrict__ idx,
                             const float* __restrict__ tok,
                             const float* __restrict__ pos,
                             float* __restrict__ x) {
    int i = blockIdx.x * blockDim.x + threadIdx.x;
    if (i >= BT * CC) return;
    int bt = i / CC, c = i % CC;
    int t = bt % TT;
    x[i] = tok[(size_t)idx[bt] * CC + c] + pos[(size_t)t * CC + c];
}

// ---------------- layernorm -> packed fp16 (interleaved) ----------------
__global__ void ln_kernel(const float* __restrict__ x,
                          const float* __restrict__ g,
                          const float* __restrict__ b,
                          uint32_t* __restrict__ out16) {
    int row = blockIdx.x;
    const float* xr = x + (size_t)row * CC;
    uint32_t* orow = out16 + (size_t)row * (CC / 2);
    __shared__ float red[256];
    __shared__ float s_mu, s_inv;
    int tid = threadIdx.x;

    float s = 0.f;
    for (int c = tid; c < CC; c += 256) s += xr[c];
    red[tid] = s; __syncthreads();
    for (int st = 128; st > 0; st >>= 1) { if (tid < st) red[tid] += red[tid + st]; __syncthreads(); }
    if (tid == 0) s_mu = red[0] / CC;
    __syncthreads();
    float mu = s_mu;

    float v = 0.f;
    for (int c = tid; c < CC; c += 256) { float d = xr[c] - mu; v += d * d; }
    red[tid] = v; __syncthreads();
    for (int st = 128; st > 0; st >>= 1) { if (tid < st) red[tid] += red[tid + st]; __syncthreads(); }
    if (tid == 0) s_inv = rsqrtf(red[0] / CC + LN_EPS);
    __syncthreads();
    float inv = s_inv;

    for (int c2 = tid; c2 < CC / 2; c2 += 256) {
        int c = 2 * c2;
        float v0 = (xr[c] - mu) * inv * g[c] + b[c];
        float v1 = (xr[c + 1] - mu) * inv * g[c + 1] + b[c + 1];
        orow[ilv(c2)] = f2h2(v0, v1);
    }
}

// ---------------- generic fp16 GEMM, cp.async 4-stage, 128x128x32 ----------------
constexpr int GNS = 4;
constexpr int GAW = 128 * 24;
constexpr int GBW = 128 * 24;
constexpr int GSTW = GAW + GBW;
constexpr int GDSM = GNS * GSTW * 4;      // 98304 bytes

template<int AM, int BMo, bool BIAS, bool RELU, bool ACC, int OM>
__global__ __launch_bounds__(256, 2)
void gemm_tc(const uint32_t* __restrict__ A, const uint32_t* __restrict__ Bw,
             const float* __restrict__ bias, void* __restrict__ Cmv,
             void* __restrict__ Caux,
             int M, int N, int Nb, int K, float alpha,
             size_t sA, size_t sB, size_t sC) {
    constexpr int BK = 32;
    extern __shared__ __align__(16) uint32_t smw[];
    uint32_t smb = (uint32_t)__cvta_generic_to_shared(smw);

    const uint32_t* Ab = A + (size_t)blockIdx.z * sA;
    const uint32_t* Bb = Bw + ((BMo == 1) ? (size_t)blockIdx.z * sB : 0);

    int bm = blockIdx.y * 128;
    int bn = blockIdx.x * 128;
    int tid = threadIdx.x;
    int wid = tid >> 5, lane = tid & 31;
    int wm = (wid & 1) * 64;
    int wn = (wid >> 1) * 32;
    int gq = lane >> 2;
    int cq = lane & 3;

    const int nIter = K / BK;

    float acc[4][4][4];
    #pragma unroll
    for (int i = 0; i < 4; i++)
        #pragma unroll
        for (int j = 0; j < 4; j++)
            #pragma unroll
            for (int t = 0; t < 4; t++) acc[i][j][t] = 0.f;

    auto issue_stage = [&](int it) {
        if (it < nIter) {
            int k0 = it * BK;
            int st = it & (GNS - 1);
            uint32_t abase = smb + (uint32_t)(st * GSTW) * 4;
            uint32_t bbase = abase + GAW * 4;
            #pragma unroll
            for (int r = 0; r < 2; r++) {
                int id = tid + r * 256;
                {
                    int m = id >> 2, k2q = (id & 3) * 4;
                    int row = bm + m;
                    const uint32_t* g;
                    if (AM == 0) {
                        g = Ab + (size_t)row * (K / 2) + (k0 / 2 + k2q);
                    } else {
                        int k = k0 + 2 * k2q;
                        int b = row / TT, t = row % TT, hh = k / HS, d = k % HS;
                        g = Ab + (((size_t)b * HH + hh) * TT + t) * (HS / 2) + d / 2;
                    }
                    cp16(abase + (uint32_t)(m * 24 + k2q) * 4, g);
                }
                if (BMo == 0) {
                    int k2 = id >> 5, n4 = (id & 31) * 4;
                    const uint32_t* g = Bb + (size_t)(k0 / 2 + k2) * Nb + bn + n4;
                    cp16(bbase + (uint32_t)(k2 * 136 + n4) * 4, g);
                } else {
                    int n = id >> 2, k2q = (id & 3) * 4;
                    const uint32_t* g = Bb + (size_t)(bn + n) * (K / 2) + (k0 / 2 + k2q);
                    cp16(bbase + (uint32_t)(n * 24 + k2q) * 4, g);
                }
            }
        }
        asm volatile("cp.async.commit_group;" ::: "memory");
    };

    #pragma unroll
    for (int s = 0; s < GNS - 1; s++) issue_stage(s);

    for (int it = 0; it < nIter; ++it) {
        asm volatile("cp.async.wait_group 2;" ::: "memory");
        __syncthreads();
        issue_stage(it + GNS - 1);

        const uint32_t* As_ = smw + (it & (GNS - 1)) * GSTW;
        const uint32_t* Bs_ = As_ + GAW;

        #pragma unroll
        for (int kk2 = 0; kk2 < BK / 2; kk2 += 8) {
            uint32_t af[4][4];
            uint32_t bf[4][2];
            #pragma unroll
            for (int i = 0; i < 4; i++) {
                int mr = wm + i * 16;
                uint2 lo = *reinterpret_cast<const uint2*>(&As_[(mr + gq) * 24 + kk2 + 2 * cq]);
                uint2 hi = *reinterpret_cast<const uint2*>(&As_[(mr + gq + 8) * 24 + kk2 + 2 * cq]);
                af[i][0] = lo.x; af[i][2] = lo.y;
                af[i][1] = hi.x; af[i][3] = hi.y;
            }
            #pragma unroll
            for (int j = 0; j < 4; j++) {
                int nc = wn + j * 8 + gq;
                if (BMo == 0) {
                    bf[j][0] = Bs_[(kk2 + cq) * 136 + nc];
                    bf[j][1] = Bs_[(kk2 + cq + 4) * 136 + nc];
                } else {
                    uint2 bv = *reinterpret_cast<const uint2*>(&Bs_[nc * 24 + kk2 + 2 * cq]);
                    bf[j][0] = bv.x; bf[j][1] = bv.y;
                }
            }
            #pragma unroll
            for (int i = 0; i < 4; i++)
                #pragma unroll
                for (int j = 0; j < 4; j++)
                    mma_fp16(acc[i][j], af[i], bf[j]);
        }
    }

    // epilogue
    float* Cf = (float*)Cmv + ((OM == 0) ? (size_t)blockIdx.z * sC : 0);
    uint32_t* Cw = (uint32_t*)Cmv + ((OM == 2) ? (size_t)blockIdx.z * sC : 0);

    #pragma unroll
    for (int i = 0; i < 4; i++) {
        int r0 = bm + wm + i * 16 + gq;
        #pragma unroll
        for (int j = 0; j < 4; j++) {
            int c0 = bn + wn + j * 8 + cq * 2;
            if (c0 >= N) continue;
            #pragma unroll
            for (int half = 0; half < 2; half++) {
                int row = r0 + half * 8;
                float v0 = acc[i][j][half * 2 + 0] * alpha;
                float v1 = acc[i][j][half * 2 + 1] * alpha;
                if (BIAS) { v0 += bias[c0]; v1 += (c0 + 1 < N) ? bias[c0 + 1] : 0.f; }
                if (RELU) { v0 = fmaxf(v0, 0.f); v1 = fmaxf(v1, 0.f); }

                if (OM == 1) {
                    int which = c0 / CC, cc = c0 % CC;
                    int b = row / TT, t = row % TT, hh = cc / HS, d = cc % HS;
                    if (which < 2) {
                        size_t base = (((size_t)b * HH + hh) * TT + t) * (HS / 2) + ilv(d / 2);
                        Cw[(size_t)which * BT * (CC / 2) + base] = f2h2(v0, v1);
                    } else {
                        __half* vt = (__half*)Caux;
                        size_t base = ((size_t)b * HH + hh) * HS;
                        int hpos = ilv(t >> 1) * 2 + (t & 1);
                        vt[(base + d) * TT + hpos] = __float2half(v0);
                        vt[(base + d + 1) * TT + hpos] = __float2half(v1);
                    }
                } else if (OM == 2) {
                    Cw[(size_t)row * (N / 2) + ilv(c0 / 2)] = f2h2(v0, v1);
                } else {
                    size_t oidx = (size_t)row * N + c0;
                    if (c0 + 1 < N) {
                        if (ACC) {
                            float2 old = *reinterpret_cast<float2*>(&Cf[oidx]);
                            v0 += old.x; v1 += old.y;
                        }
                        *reinterpret_cast<float2*>(&Cf[oidx]) = make_float2(v0, v1);
                    } else {
                        if (ACC) v0 += Cf[oidx];
                        Cf[oidx] = v0;
                    }
                }
            }
        }
    }
}

// ---------------- fused ATT GEMM + causal softmax ----------------
// scores = Q@K^T * rs, causal mask, softmax along keys, write interleaved fp16.
// BM=64, BN=256 (full key dim per CTA), K=HS=96 fully prefetched (3 stages).
// 8 warps along N (wn = wid*32). grid: (1, TT/64, B*H).
constexpr int AT_AW = 64 * 24;             // 1536 words / stage
constexpr int AT_BW = 256 * 24;            // 6144 words / stage
constexpr int AT_STW = AT_AW + AT_BW;      // 7680 words
constexpr int AT_DSM = 3 * AT_STW * 4;     // 92160 bytes

__global__ __launch_bounds__(256, 2)
void attsm_kernel(const uint32_t* __restrict__ q16, const uint32_t* __restrict__ k16,
                  uint32_t* __restrict__ att16, float rs) {
    extern __shared__ __align__(16) uint32_t smw[];
    uint32_t smb = (uint32_t)__cvta_generic_to_shared(smw);

    const uint32_t* Ab = q16 + (size_t)blockIdx.z * TT * (HS / 2);
    const uint32_t* Bb = k16 + (size_t)blockIdx.z * TT * (HS / 2);
    uint32_t* Ob = att16 + (size_t)blockIdx.z * TT * (TT / 2);

    int bm = blockIdx.y * 64;
    int tid = threadIdx.x;
    int wid = tid >> 5, lane = tid & 31;
    int wn = wid * 32;
    int gq = lane >> 4 == 0 ? (lane >> 2) : (lane >> 2);  // lane>>2
    gq = lane >> 2;
    int cq = lane & 3;

    // ---- stage all of K=96 (3 tiles) ----
    #pragma unroll
    for (int st = 0; st < 3; st++) {
        int k0 = st * 32;
        uint32_t abase = smb + (uint32_t)(st * AT_STW) * 4;
        uint32_t bbase = abase + AT_AW * 4;
        {   // A: 64 rows x 4 chunks = 256
            int m = tid >> 2, k2q = (tid & 3) * 4;
            cp16(abase + (uint32_t)(m * 24 + k2q) * 4,
                 Ab + (size_t)(bm + m) * (HS / 2) + (k0 / 2 + k2q));
        }
        #pragma unroll
        for (int r = 0; r < 4; r++) {   // B: 256 n x 4 chunks = 1024
            int id = tid + r * 256;
            int n = id >> 2, k2q = (id & 3) * 4;
            cp16(bbase + (uint32_t)(n * 24 + k2q) * 4,
                 Bb + (size_t)n * (HS / 2) + (k0 / 2 + k2q));
        }
        asm volatile("cp.async.commit_group;" ::: "memory");
    }
    asm volatile("cp.async.wait_group 0;" ::: "memory");
    __syncthreads();

    float acc[4][4][4];
    #pragma unroll
    for (int i = 0; i < 4; i++)
        #pragma unroll
        for (int j = 0; j < 4; j++)
            #pragma unroll
            for (int t = 0; t < 4; t++) acc[i][j][t] = 0.f;

    if (wn <= bm + 63) {    // fully-masked warps skip MMA
        #pragma unroll
        for (int st = 0; st < 3; st++) {
            const uint32_t* As_ = smw + st * AT_STW;
            const uint32_t* Bs_ = As_ + AT_AW;
            #pragma unroll
            for (int kk2 = 0; kk2 < 16; kk2 += 8) {
                uint32_t af[4][4];
                uint32_t bf[4][2];
                #pragma unroll
                for (int i = 0; i < 4; i++) {
                    int mr = i * 16;
                    uint2 lo = *reinterpret_cast<const uint2*>(&As_[(mr + gq) * 24 + kk2 + 2 * cq]);
                    uint2 hi = *reinterpret_cast<const uint2*>(&As_[(mr + gq + 8) * 24 + kk2 + 2 * cq]);
                    af[i][0] = lo.x; af[i][2] = lo.y;
                    af[i][1] = hi.x; af[i][3] = hi.y;
                }
                #pragma unroll
                for (int j = 0; j < 4; j++) {
                    int nc = wn + j * 8 + gq;
                    uint2 bv = *reinterpret_cast<const uint2*>(&Bs_[nc * 24 + kk2 + 2 * cq]);
                    bf[j][0] = bv.x; bf[j][1] = bv.y;
                }
                #pragma unroll
                for (int i = 0; i < 4; i++)
                    #pragma unroll
                    for (int j = 0; j < 4; j++)
                        mma_fp16(acc[i][j], af[i], bf[j]);
            }
        }
    }
    __syncthreads();   // before reusing smem for reductions

    float* sred = (float*)smw;   // [8 warps][64 rows]

    // ---- row max (masked) ----
    float rmax[4][2];
    #pragma unroll
    for (int i = 0; i < 4; i++)
        #pragma unroll
        for (int half = 0; half < 2; half++) {
            int rl = i * 16 + gq + half * 8;
            int qi = bm + rl;
            float m = -1e30f;
            #pragma unroll
            for (int j = 0; j < 4; j++)
                #pragma unroll
                for (int p = 0; p < 2; p++) {
                    int ct = wn + j * 8 + cq * 2 + p;
                    if (ct <= qi) m = fmaxf(m, acc[i][j][half * 2 + p] * rs);
                }
            m = fmaxf(m, __shfl_xor_sync(0xffffffffu, m, 1));
            m = fmaxf(m, __shfl_xor_sync(0xffffffffu, m, 2));
            rmax[i][half] = m;
        }
    if (cq == 0) {
        #pragma unroll
        for (int i = 0; i < 4; i++)
            #pragma unroll
            for (int half = 0; half < 2; half++)
                sred[wid * 64 + i * 16 + gq + half * 8] = rmax[i][half];
    }
    __syncthreads();
    #pragma unroll
    for (int i = 0; i < 4; i++)
        #pragma unroll
        for (int half = 0; half < 2; half++) {
            int rl = i * 16 + gq + half * 8;
            float m = -1e30f;
            #pragma unroll
            for (int w = 0; w < 8; w++) m = fmaxf(m, sred[w * 64 + rl]);
            rmax[i][half] = m;
        }
    __syncthreads();

    // ---- exp + row sum ----
    float rsum[4][2];
    #pragma unroll
    for (int i = 0; i < 4; i++)
        #pragma unroll
        for (int half = 0; half < 2; half++) {
            int rl = i * 16 + gq + half * 8;
            int qi = bm + rl;
            float s = 0.f;
            #pragma unroll
            for (int j = 0; j < 4; j++)
                #pragma unroll
                for (int p = 0; p < 2; p++) {
                    int ct = wn + j * 8 + cq * 2 + p;
                    float e = (ct <= qi) ? expf(acc[i][j][half * 2 + p] * rs - rmax[i][half]) : 0.f;
                    acc[i][j][half * 2 + p] = e;
                    s += e;
                }
            s += __shfl_xor_sync(0xffffffffu, s, 1);
            s += __shfl_xor_sync(0xffffffffu, s, 2);
            rsum[i][half] = s;
        }
    if (cq == 0) {
        #pragma unroll
        for (int i = 0; i < 4; i++)
            #pragma unroll
            for (int half = 0; half < 2; half++)
                sred[wid * 64 + i * 16 + gq + half * 8] = rsum[i][half];
    }
    __syncthreads();

    // ---- normalize + write interleaved fp16 ----
    #pragma unroll
    for (int i = 0; i < 4; i++)
        #pragma unroll
        for (int half = 0; half < 2; half++) {
            int rl = i * 16 + gq + half * 8;
            int qi = bm + rl;
            float s = 0.f;
            #pragma unroll
            for (int w = 0; w < 8; w++) s += sred[w * 64 + rl];
            float inv = 1.f / s;
            #pragma unroll
            for (int j = 0; j < 4; j++) {
                int c0 = wn + j * 8 + cq * 2;
                Ob[(size_t)qi * (TT / 2) + ilv(c0 / 2)] =
                    f2h2(acc[i][j][half * 2 + 0] * inv, acc[i][j][half * 2 + 1] * inv);
            }
        }
}

// ---------------- loss ----------------
__global__ void rowloss_kernel(const float* __restrict__ logits,
                               const int* __restrict__ targets,
                               float* __restrict__ rowloss) {
    int r = blockIdx.x;
    const float* lr = logits + (size_t)r * VV;
    int tid = threadIdx.x;
    __shared__ float red[256];
    __shared__ float s_mx;

    float mx = -1e30f;
    for (int c = tid; c < VV; c += 256) mx = fmaxf(mx, lr[c]);
    red[tid] = mx; __syncthreads();
    for (int st = 128; st > 0; st >>= 1) { if (tid < st) red[tid] = fmaxf(red[tid], red[tid + st]); __syncthreads(); }
    if (tid == 0) s_mx = red[0];
    __syncthreads();
    mx = s_mx;

    float s = 0.f;
    for (int c = tid; c < VV; c += 256) s += expf(lr[c] - mx);
    red[tid] = s; __syncthreads();
    for (int st = 128; st > 0; st >>= 1) { if (tid < st) red[tid] += red[tid + st]; __syncthreads(); }
    if (tid == 0) {
        int t = targets[r];
        rowloss[r] = -(lr[t] - mx - logf(red[0]));
    }
}

__global__ void lossreduce_kernel(const float* __restrict__ rowloss, float* __restrict__ out) {
    __shared__ float red[256];
    int tid = threadIdx.x;
    float s = 0.f;
    for (int r = tid; r < BT; r += 256) s += rowloss[r];
    red[tid] = s; __syncthreads();
    for (int st = 128; st > 0; st >>= 1) { if (tid < st) red[tid] += red[tid + st]; __syncthreads(); }
    if (tid == 0) out[0] = red[0] / BT;
}

// ---------------- host ----------------
static inline dim3 ggrid(int M, int N, int batch) {
    return dim3((N + 127) / 128, (M + 127) / 128, batch);
}

extern "C" void kernel_launch(void* const* d_in, const int* in_sizes, int n_in,
                              void* d_out, int out_size) {
    const int*   idx     = (const int*)  d_in[0];
    const int*   targets = (const int*)  d_in[1];
    const float* tok_emb = (const float*)d_in[2];
    const float* pos_emb = (const float*)d_in[3];
    const float* Wq      = (const float*)d_in[4];
    const float* Wk      = (const float*)d_in[5];
    const float* Wv      = (const float*)d_in[6];
    const float* Wproj   = (const float*)d_in[7];
    const float* bproj   = (const float*)d_in[8];
    const float* W1      = (const float*)d_in[9];
    const float* b1      = (const float*)d_in[10];
    const float* W2      = (const float*)d_in[11];
    const float* b2      = (const float*)d_in[12];
    const float* ln1_g   = (const float*)d_in[13];
    const float* ln1_b   = (const float*)d_in[14];
    const float* ln2_g   = (const float*)d_in[15];
    const float* ln2_b   = (const float*)d_in[16];
    const float* lnf_g   = (const float*)d_in[17];
    const float* lnf_b   = (const float*)d_in[18];
    const float* Wlm     = (const float*)d_in[19];
    const float* blm     = (const float*)d_in[20];
    float* out = (float*)d_out;

    float* x    = nullptr; cudaGetSymbolAddress((void**)&x,    g_x);
    uint32_t* h16  = nullptr; cudaGetSymbolAddress((void**)&h16,  g_h16);
    uint32_t* qk16 = nullptr; cudaGetSymbolAddress((void**)&qk16, g_qk16);
    uint32_t* v16t = nullptr; cudaGetSymbolAddress((void**)&v16t, g_v16t);
    uint32_t* att16 = nullptr; cudaGetSymbolAddress((void**)&att16, g_att16);
    uint32_t* a16  = nullptr; cudaGetSymbolAddress((void**)&a16,  g_a16);
    uint32_t* ff16 = nullptr; cudaGetSymbolAddress((void**)&ff16, g_ff16);
    float* rowloss = nullptr; cudaGetSymbolAddress((void**)&rowloss, g_rowloss);
    uint32_t* wqkv16  = nullptr; cudaGetSymbolAddress((void**)&wqkv16,  g_wqkv16);
    uint32_t* wproj16 = nullptr; cudaGetSymbolAddress((void**)&wproj16, g_wproj16);
    uint32_t* w116    = nullptr; cudaGetSymbolAddress((void**)&w116,    g_w116);
    uint32_t* w216    = nullptr; cudaGetSymbolAddress((void**)&w216,    g_w216);
    uint32_t* wlm16   = nullptr; cudaGetSymbolAddress((void**)&wlm16,   g_wlm16);

    const float rs = rsqrtf((float)HS);
    uint32_t* q16 = qk16;
    uint32_t* k16 = qk16 + (size_t)BT * (CC / 2);

    auto kQKV  = gemm_tc<0, 0, false, false, false, 1>;
    auto kAV   = gemm_tc<0, 1, false, false, false, 2>;
    auto kPROJ = gemm_tc<1, 0, true,  false, true,  0>;
    auto kFF1  = gemm_tc<0, 0, true,  true,  false, 2>;
    auto kFF2  = gemm_tc<0, 0, true,  false, true,  0>;
    auto kLM   = gemm_tc<0, 0, true,  false, false, 0>;
    cudaFuncSetAttribute(kQKV,  cudaFuncAttributeMaxDynamicSharedMemorySize, GDSM);
    cudaFuncSetAttribute(kAV,   cudaFuncAttributeMaxDynamicSharedMemorySize, GDSM);
    cudaFuncSetAttribute(kPROJ, cudaFuncAttributeMaxDynamicSharedMemorySize, GDSM);
    cudaFuncSetAttribute(kFF1,  cudaFuncAttributeMaxDynamicSharedMemorySize, GDSM);
    cudaFuncSetAttribute(kFF2,  cudaFuncAttributeMaxDynamicSharedMemorySize, GDSM);
    cudaFuncSetAttribute(kLM,   cudaFuncAttributeMaxDynamicSharedMemorySize, GDSM);
    cudaFuncSetAttribute(attsm_kernel, cudaFuncAttributeMaxDynamicSharedMemorySize, AT_DSM);

    // ---- pack weights ----
    {
        size_t n;
        n = (size_t)LL * (CC / 2) * (3 * CC);
        pack_qkv_kernel<<<(unsigned)((n + 255) / 256), 256>>>(Wq, Wk, Wv, wqkv16);
        n = (size_t)LL * (CC / 2) * CC;
        pack_w_kernel<<<(unsigned)((n + 255) / 256), 256>>>(Wproj, wproj16, LL * CC / 2, CC, CC);
        n = (size_t)LL * (CC / 2) * FFD;
        pack_w_kernel<<<(unsigned)((n + 255) / 256), 256>>>(W1, w116, LL * CC / 2, FFD, FFD);
        n = (size_t)LL * (FFD / 2) * CC;
        pack_w_kernel<<<(unsigned)((n + 255) / 256), 256>>>(W2, w216, LL * FFD / 2, CC, CC);
        n = (size_t)(CC / 2) * VVP;
        pack_w_kernel<<<(unsigned)((n + 255) / 256), 256>>>(Wlm, wlm16, CC / 2, VV, VVP);
    }

    embed_kernel<<<(BT * CC + 255) / 256, 256>>>(idx, tok_emb, pos_emb, x);

    for (int l = 0; l < LL; l++) {
        const uint32_t* wqkv = wqkv16 + (size_t)l * (CC / 2) * (3 * CC);
        const uint32_t* wp   = wproj16 + (size_t)l * (CC / 2) * CC;
        const uint32_t* w1   = w116 + (size_t)l * (CC / 2) * FFD;
        const uint32_t* w2   = w216 + (size_t)l * (FFD / 2) * CC;
        const float* bp  = bproj + (size_t)l * CC;
        const float* bb1 = b1 + (size_t)l * FFD;
        const float* bb2 = b2 + (size_t)l * CC;

        ln_kernel<<<BT, 256>>>(x, ln1_g + (size_t)l * CC, ln1_b + (size_t)l * CC, h16);

        kQKV<<<ggrid(BT, 3 * CC, 1), 256, GDSM>>>(
            h16, wqkv, nullptr, qk16, v16t, BT, 3 * CC, 3 * CC, CC, 1.f, 0, 0, 0);

        // fused scores + causal softmax -> att16
        attsm_kernel<<<dim3(1, TT / 64, BB * HH), 256, AT_DSM>>>(q16, k16, att16, rs);

        kAV<<<ggrid(TT, HS, BB * HH), 256, GDSM>>>(
            att16, v16t, nullptr, a16, nullptr, TT, HS, HS, TT, 1.f,
            (size_t)TT * (TT / 2), (size_t)HS * (TT / 2), (size_t)TT * (HS / 2));

        kPROJ<<<ggrid(BT, CC, 1), 256, GDSM>>>(
            a16, wp, bp, x, nullptr, BT, CC, CC, CC, 1.f, 0, 0, 0);

        ln_kernel<<<BT, 256>>>(x, ln2_g + (size_t)l * CC, ln2_b + (size_t)l * CC, h16);

        kFF1<<<ggrid(BT, FFD, 1), 256, GDSM>>>(
            h16, w1, bb1, ff16, nullptr, BT, FFD, FFD, CC, 1.f, 0, 0, 0);

        kFF2<<<ggrid(BT, CC, 1), 256, GDSM>>>(
            ff16, w2, bb2, x, nullptr, BT, CC, CC, FFD, 1.f, 0, 0, 0);
    }

    ln_kernel<<<BT, 256>>>(x, lnf_g, lnf_b, h16);

    kLM<<<ggrid(BT, VVP, 1), 256, GDSM>>>(
        h16, wlm16, blm, out, nullptr, BT, VV, VVP, CC, 1.f, 0, 0, 0);

    rowloss_kernel<<<BT, 256>>>(out, targets, rowloss);
    if ((long long)out_size > (long long)BT * VV) {
        lossreduce_kernel<<<1, 256>>>(rowloss, out + (size_t)BT * VV);
    }
}